// round 2
// baseline (speedup 1.0000x reference)
#include <cuda_runtime.h>
#include <cuda_bf16.h>
#include <math.h>

// Problem constants
#define BB   32
#define TT   32
#define HH   28
#define WW   28
#define FF   48
#define UU   8
#define EPSB 1e-3f
#define NFRAMES (BB*TT)          // 1024
#define FRAME_PIX (HH*WW)        // 784

typedef unsigned long long ull;

// ---------------------------------------------------------------------------
// Packed-f32 helpers (Blackwell f32x2 pipe; PTX-only, ptxas won't auto-fuse)
// ---------------------------------------------------------------------------
__device__ __forceinline__ ull pk2(float lo, float hi) {
    ull r;
    asm("mov.b64 %0, {%1, %2};" : "=l"(r) : "f"(lo), "f"(hi));
    return r;
}
__device__ __forceinline__ void ffma2(ull& d, ull a, ull b) {
    asm("fma.rn.f32x2 %0, %1, %2, %0;" : "+l"(d) : "l"(a), "l"(b));
}
__device__ __forceinline__ float2 unpk(ull v) {
    float2 f;
    asm("mov.b64 {%0, %1}, %2;" : "=f"(f.x), "=f"(f.y) : "l"(v));
    return f;
}
__device__ __forceinline__ unsigned smem_u32(const void* p) {
    return (unsigned)__cvta_generic_to_shared(p);
}
// 16B shared load: {v(ci),v(ci+1)} , {v(ci+2),v(ci+3)} as two packed pairs
__device__ __forceinline__ void lds_v2u64(ull& a, ull& b, unsigned addr) {
    asm volatile("ld.shared.v2.u64 {%0, %1}, [%2];" : "=l"(a), "=l"(b) : "r"(addr));
}

// ---------------------------------------------------------------------------
// Scratch (static __device__ arrays; allocation APIs are forbidden)
// ---------------------------------------------------------------------------
__device__ float g_act1[NFRAMES * FRAME_PIX * FF];   // conv1 out, [frame][h*28+w][co]
__device__ float g_act2[NFRAMES * FRAME_PIX * FF];   // conv2 out, same layout
__device__ float g_feats[NFRAMES * 2 * FF];          // per-(frame,band) pooled partials

// ---------------------------------------------------------------------------
// Kernel 1: conv1 (C=1 -> 48) + ReLU. One block per frame.
// ---------------------------------------------------------------------------
__global__ void conv1_kernel(const float* __restrict__ x,
                             const float* __restrict__ w1,
                             const float* __restrict__ b1)
{
    __shared__ float s_f[FRAME_PIX];
    __shared__ float s_w[9 * FF];
    __shared__ float s_b[FF];

    const int frame = blockIdx.x;
    const int tid   = threadIdx.x;

    for (int i = tid; i < FRAME_PIX; i += 256) s_f[i] = x[frame * FRAME_PIX + i];
    for (int i = tid; i < 9 * FF;   i += 256) s_w[i] = w1[i];
    if (tid < FF) s_b[tid] = b1[tid];
    __syncthreads();

    float* outp = g_act1 + (size_t)frame * FRAME_PIX * FF;
    for (int idx = tid; idx < FRAME_PIX * FF; idx += 256) {
        const int co = idx % FF;
        const int p  = idx / FF;
        const int h  = p / WW;
        const int w  = p % WW;
        float acc = s_b[co];
        #pragma unroll
        for (int dy = 0; dy < 3; ++dy) {
            const int hh = h + dy - 1;
            if ((unsigned)hh < (unsigned)HH) {
                #pragma unroll
                for (int dx = 0; dx < 3; ++dx) {
                    const int wx = w + dx - 1;
                    if ((unsigned)wx < (unsigned)WW)
                        acc += s_f[hh * WW + wx] * s_w[(dy * 3 + dx) * FF + co];
                }
            }
        }
        outp[idx] = fmaxf(acc, 0.f);
    }
}

// ---------------------------------------------------------------------------
// Kernel 2/3: 48->48 conv + ReLU, f32x2-packed over ci.
// One block per (frame, 14-row band).
// PHASE 0: reads g_act1, writes g_act2.
// PHASE 1: reads g_act2, pools ReLU output per (frame, band, co) into g_feats.
//
// SMEM: input band [16 rows][30 cols][48 ci] (zero-padded halo) + full
// weight tile [3][3][48][48]. Thread: co = tid%48, g = tid/48 ->
// (col chunk of 7, row parity). Each thread: 7 rows x 7 cols, one co.
// Inner unit (dy, ci-quad): 9x ld.shared.v2.u64 (vectorized input, 4 ci) +
// 12 scalar weight LDS + 6 packs + 42 fma.rn.f32x2 (84 MACs).
// ---------------------------------------------------------------------------
#define BAND_ROWS 14
#define IN_ROWS   16
#define IN_COLS   30
#define CONV_THREADS 384
#define SMEM_IN_FLOATS (IN_ROWS * IN_COLS * FF)        // 23040
#define SMEM_W_FLOATS  (9 * FF * FF)                   // 20736
#define CONV_SMEM_BYTES ((SMEM_IN_FLOATS + SMEM_W_FLOATS) * 4)

template <int PHASE>
__global__ void __launch_bounds__(CONV_THREADS, 1)
conv48_kernel(const float* __restrict__ w,
              const float* __restrict__ bias)
{
    extern __shared__ float sm[];
    float* s_in = sm;                       // [16][30][48]
    float* s_w  = sm + SMEM_IN_FLOATS;      // [3][3][48][48]
    __shared__ float s_red[8 * FF];

    const int frame = blockIdx.x >> 1;
    const int band  = blockIdx.x & 1;
    const int tid   = threadIdx.x;
    const int r0f   = band * BAND_ROWS - 1;      // global row of buffer row 0

    const float* in_act = (PHASE == 0) ? g_act1 : g_act2;
    const float* fin = in_act + (size_t)frame * FRAME_PIX * FF;

    // Load input band (zero-fill halo)
    for (int i = tid; i < SMEM_IN_FLOATS; i += CONV_THREADS) {
        const int lr  = i / (IN_COLS * FF);
        const int rem = i - lr * (IN_COLS * FF);
        const int cc  = rem / FF;
        const int ci  = rem - cc * FF;
        const int hh  = r0f + lr;
        const int wcol = cc - 1;
        float v = 0.f;
        if ((unsigned)hh < (unsigned)HH && (unsigned)wcol < (unsigned)WW)
            v = fin[(hh * WW + wcol) * FF + ci];
        s_in[i] = v;
    }
    for (int i = tid; i < SMEM_W_FLOATS; i += CONV_THREADS) s_w[i] = w[i];
    __syncthreads();

    const unsigned s_in_b = smem_u32(s_in);

    const int co   = tid % FF;
    const int g    = tid / FF;          // 0..7
    const int w0   = (g & 3) * 7;       // column chunk start
    const int rpar = g >> 2;            // row parity within band
    const float bco = bias[co];

    float pool = 0.f;

    for (int rr = 0; rr < 7; ++rr) {
        const int hl = rpar + rr * 2;   // local output row 0..13
        ull accP[7];
        #pragma unroll
        for (int j = 0; j < 7; ++j) accP[j] = 0ull;

        #pragma unroll
        for (int dy = 0; dy < 3; ++dy) {
            // buffer row hl+dy, starting buffer col w0 (maps to global col w0-1)
            const unsigned srb = s_in_b + (unsigned)(((hl + dy) * IN_COLS + w0) * FF) * 4u;
            const float* wp = s_w + dy * 3 * (FF * FF) + co;

            #pragma unroll 1
            for (int ci = 0; ci < FF; ci += 4) {
                ull vA[9], vB[9];               // {ci,ci+1}, {ci+2,ci+3} per col
                #pragma unroll
                for (int j = 0; j < 9; ++j)
                    lds_v2u64(vA[j], vB[j], srb + (unsigned)(j * FF + ci) * 4u);

                ull w01[3], w23[3];
                #pragma unroll
                for (int dx = 0; dx < 3; ++dx) {
                    const float* wq = wp + dx * (FF * FF) + ci * FF;
                    w01[dx] = pk2(wq[0],      wq[FF]);
                    w23[dx] = pk2(wq[2 * FF], wq[3 * FF]);
                }

                #pragma unroll
                for (int j = 0; j < 7; ++j) {
                    ffma2(accP[j], vA[j],     w01[0]);
                    ffma2(accP[j], vB[j],     w23[0]);
                    ffma2(accP[j], vA[j + 1], w01[1]);
                    ffma2(accP[j], vB[j + 1], w23[1]);
                    ffma2(accP[j], vA[j + 2], w01[2]);
                    ffma2(accP[j], vB[j + 2], w23[2]);
                }
            }
        }

        const int hg = band * BAND_ROWS + hl;    // global output row
        if (PHASE == 0) {
            float* op = g_act2 + ((size_t)(frame * HH + hg) * WW + w0) * FF + co;
            #pragma unroll
            for (int j = 0; j < 7; ++j) {
                const float2 f = unpk(accP[j]);
                op[j * FF] = fmaxf(f.x + f.y + bco, 0.f);
            }
        } else {
            #pragma unroll
            for (int j = 0; j < 7; ++j) {
                const float2 f = unpk(accP[j]);
                pool += fmaxf(f.x + f.y + bco, 0.f);
            }
        }
    }

    if (PHASE == 1) {
        s_red[g * FF + co] = pool;
        __syncthreads();
        if (tid < FF) {
            float s = 0.f;
            #pragma unroll
            for (int gg = 0; gg < 8; ++gg) s += s_red[gg * FF + tid];
            g_feats[(frame * 2 + band) * FF + tid] = s;   // per-band partial, no atomics
        }
    }
}

// ---------------------------------------------------------------------------
// Kernel 4: LSTM over T=32, plus BN2 + output head. Single block, 256 threads.
// Thread = (b = tid/8, u = tid%8). BN1 (post-pool affine) folded into xt load.
// ---------------------------------------------------------------------------
__global__ void lstm_kernel(const float* __restrict__ wf,  const float* __restrict__ bf,
                            const float* __restrict__ wi1, const float* __restrict__ bi1,
                            const float* __restrict__ wi2, const float* __restrict__ bi2,
                            const float* __restrict__ wo,  const float* __restrict__ bo,
                            const float* __restrict__ bn1_g, const float* __restrict__ bn1_b,
                            const float* __restrict__ bn1_m, const float* __restrict__ bn1_v,
                            const float* __restrict__ bn2_g, const float* __restrict__ bn2_b,
                            const float* __restrict__ bn2_m, const float* __restrict__ bn2_v,
                            const float* __restrict__ w_out, const float* __restrict__ b_out,
                            float* __restrict__ out)
{
    __shared__ float s_x[BB][FF];
    __shared__ float s_h[BB][UU];
    __shared__ float s_w[4][FF + UU][UU];
    __shared__ float s_bias[4][UU];
    __shared__ float s_sc1[FF], s_sh1[FF];

    const int tid = threadIdx.x;
    const int b   = tid >> 3;
    const int u   = tid & 7;

    for (int i = tid; i < (FF + UU) * UU; i += 256) {
        const int r = i / UU, cu = i % UU;
        s_w[0][r][cu] = wf[i];
        s_w[1][r][cu] = wi1[i];
        s_w[2][r][cu] = wi2[i];
        s_w[3][r][cu] = wo[i];
    }
    if (tid < 4 * UU) {
        const float* bs[4] = {bf, bi1, bi2, bo};
        s_bias[tid >> 3][tid & 7] = bs[tid >> 3][tid & 7];
    }
    if (tid < FF) {
        const float sc = bn1_g[tid] * rsqrtf(bn1_v[tid] + EPSB);
        s_sc1[tid] = sc * (1.f / (float)FRAME_PIX);   // fold 1/784 mean
        s_sh1[tid] = bn1_b[tid] - bn1_m[tid] * sc;
    }
    s_h[b][u] = 0.f;
    float c = 0.f;

    // BN2 + output head folded into per-u coefficient + scalar constant
    const float sc2  = bn2_g[u] * rsqrtf(bn2_v[u] + EPSB);
    const float coef = sc2 * w_out[u];
    float outc = b_out[0];
    #pragma unroll
    for (int j = 0; j < UU; ++j) {
        const float s2 = bn2_g[j] * rsqrtf(bn2_v[j] + EPSB);
        outc += (bn2_b[j] - bn2_m[j] * s2) * w_out[j];
    }
    __syncthreads();

    for (int t = 0; t < TT; ++t) {
        for (int i = tid; i < BB * FF; i += 256) {
            const int bb = i / FF, co = i % FF;
            const int fr = (bb << 5) + t;
            const float ps = g_feats[(fr * 2) * FF + co] + g_feats[(fr * 2 + 1) * FF + co];
            s_x[bb][co] = ps * s_sc1[co] + s_sh1[co];
        }
        __syncthreads();

        float af = s_bias[0][u], ai = s_bias[1][u];
        float ag = s_bias[2][u], ao = s_bias[3][u];
        #pragma unroll 8
        for (int k = 0; k < FF; ++k) {
            const float xv = s_x[b][k];
            af += xv * s_w[0][k][u];
            ai += xv * s_w[1][k][u];
            ag += xv * s_w[2][k][u];
            ao += xv * s_w[3][k][u];
        }
        #pragma unroll
        for (int j = 0; j < UU; ++j) {
            const float hv = s_h[b][j];
            af += hv * s_w[0][FF + j][u];
            ai += hv * s_w[1][FF + j][u];
            ag += hv * s_w[2][FF + j][u];
            ao += hv * s_w[3][FF + j][u];
        }
        const float fg = 1.f / (1.f + expf(-af));
        const float ig = 1.f / (1.f + expf(-ai));
        const float gg = tanhf(ag);
        const float og = 1.f / (1.f + expf(-ao));
        c = fg * c + ig * gg;
        const float hn = og * tanhf(c);

        __syncthreads();           // everyone done reading old s_h
        s_h[b][u] = hn;

        float p = hn * coef;       // segmented (8-lane) reduce via xor shuffles
        p += __shfl_xor_sync(0xffffffffu, p, 4);
        p += __shfl_xor_sync(0xffffffffu, p, 2);
        p += __shfl_xor_sync(0xffffffffu, p, 1);
        if (u == 0) out[(b << 5) + t] = p + outc;
        __syncthreads();           // orders s_h writes / s_x reuse
    }
}

// ---------------------------------------------------------------------------
// Launch
// ---------------------------------------------------------------------------
extern "C" void kernel_launch(void* const* d_in, const int* in_sizes, int n_in,
                              void* d_out, int out_size)
{
    const float* x     = (const float*)d_in[0];
    const float* w1    = (const float*)d_in[1];
    const float* b1    = (const float*)d_in[2];
    const float* w2    = (const float*)d_in[3];
    const float* b2    = (const float*)d_in[4];
    const float* w3    = (const float*)d_in[5];
    const float* b3    = (const float*)d_in[6];
    const float* bn1_g = (const float*)d_in[7];
    const float* bn1_b = (const float*)d_in[8];
    const float* bn1_m = (const float*)d_in[9];
    const float* bn1_v = (const float*)d_in[10];
    const float* wf    = (const float*)d_in[11];
    const float* bf    = (const float*)d_in[12];
    const float* wi1   = (const float*)d_in[13];
    const float* bi1   = (const float*)d_in[14];
    const float* wi2   = (const float*)d_in[15];
    const float* bi2   = (const float*)d_in[16];
    const float* wo    = (const float*)d_in[17];
    const float* bo    = (const float*)d_in[18];
    const float* bn2_g = (const float*)d_in[19];
    const float* bn2_b = (const float*)d_in[20];
    const float* bn2_m = (const float*)d_in[21];
    const float* bn2_v = (const float*)d_in[22];
    const float* w_out = (const float*)d_in[23];
    const float* b_out = (const float*)d_in[24];
    float* out = (float*)d_out;

    cudaFuncSetAttribute(conv48_kernel<0>,
                         cudaFuncAttributeMaxDynamicSharedMemorySize, CONV_SMEM_BYTES);
    cudaFuncSetAttribute(conv48_kernel<1>,
                         cudaFuncAttributeMaxDynamicSharedMemorySize, CONV_SMEM_BYTES);

    conv1_kernel<<<NFRAMES, 256>>>(x, w1, b1);
    conv48_kernel<0><<<NFRAMES * 2, CONV_THREADS, CONV_SMEM_BYTES>>>(w2, b2);
    conv48_kernel<1><<<NFRAMES * 2, CONV_THREADS, CONV_SMEM_BYTES>>>(w3, b3);
    lstm_kernel<<<1, 256>>>(wf, bf, wi1, bi1, wi2, bi2, wo, bo,
                            bn1_g, bn1_b, bn1_m, bn1_v,
                            bn2_g, bn2_b, bn2_m, bn2_v,
                            w_out, b_out, out);
}

// round 5
// speedup vs baseline: 1.8023x; 1.8023x over previous
#include <cuda_runtime.h>
#include <cuda_bf16.h>
#include <cstdint>
#include <math.h>

// Problem constants
#define BB   32
#define TT   32
#define HH   28
#define WW   28
#define FF   48
#define UU   8
#define EPSB 1e-3f
#define NFRAMES (BB*TT)            // 1024
#define FRAME_PIX (HH*WW)          // 784
#define PW   30                    // padded width
#define PROWS (PW*PW)              // 900 padded pixel-rows per frame

// ---------------------------------------------------------------------------
// Warp-MMA helpers (baseline sm_80+ ISA — assembles for plain sm_100)
// ---------------------------------------------------------------------------
__device__ __forceinline__ uint32_t smem_u32(const void* p) {
    return (uint32_t)__cvta_generic_to_shared(p);
}
__device__ __forceinline__ void ldmx4(uint32_t a[4], uint32_t addr) {
    asm volatile("ldmatrix.sync.aligned.m8n8.x4.shared.b16 {%0,%1,%2,%3}, [%4];"
                 : "=r"(a[0]), "=r"(a[1]), "=r"(a[2]), "=r"(a[3]) : "r"(addr));
}
__device__ __forceinline__ void mma_bf16(float c[4], const uint32_t a[4],
                                         uint32_t b0, uint32_t b1) {
    asm volatile("mma.sync.aligned.m16n8k16.row.col.f32.bf16.bf16.f32 "
                 "{%0,%1,%2,%3},{%4,%5,%6,%7},{%8,%9},{%0,%1,%2,%3};"
                 : "+f"(c[0]), "+f"(c[1]), "+f"(c[2]), "+f"(c[3])
                 : "r"(a[0]), "r"(a[1]), "r"(a[2]), "r"(a[3]), "r"(b0), "r"(b1));
}
__device__ __forceinline__ void split_bf16(float y, __nv_bfloat16& hi, __nv_bfloat16& lo) {
    hi = __float2bfloat16_rn(y);
    lo = __float2bfloat16_rn(y - __bfloat162float(hi));
}

// ---------------------------------------------------------------------------
// Scratch: hi/lo bf16 activations, dense [frame][900 padded rows][48]
// (halo rows never written; the slab loader zero-fills them on read)
// ---------------------------------------------------------------------------
__device__ __align__(16) __nv_bfloat16 g_a1h[NFRAMES * PROWS * FF];
__device__ __align__(16) __nv_bfloat16 g_a1l[NFRAMES * PROWS * FF];
__device__ __align__(16) __nv_bfloat16 g_a2h[NFRAMES * PROWS * FF];
__device__ __align__(16) __nv_bfloat16 g_a2l[NFRAMES * PROWS * FF];
__device__ float g_feats[NFRAMES * 2 * FF];   // per-(frame,half) pooled partials

// ---------------------------------------------------------------------------
// Kernel 1: conv1 (C=1 -> 48) + ReLU, direct fp32; writes hi/lo bf16 split.
// ---------------------------------------------------------------------------
__global__ void conv1_kernel(const float* __restrict__ x,
                             const float* __restrict__ w1,
                             const float* __restrict__ b1)
{
    __shared__ float s_f[FRAME_PIX];
    __shared__ float s_w[9 * FF];
    __shared__ float s_b[FF];

    const int frame = blockIdx.x;
    const int tid   = threadIdx.x;

    for (int i = tid; i < FRAME_PIX; i += 256) s_f[i] = x[frame * FRAME_PIX + i];
    for (int i = tid; i < 9 * FF;   i += 256) s_w[i] = w1[i];
    if (tid < FF) s_b[tid] = b1[tid];
    __syncthreads();

    const size_t fbase = (size_t)frame * PROWS * FF;
    for (int idx = tid; idx < FRAME_PIX * FF; idx += 256) {
        const int co = idx % FF;
        const int p  = idx / FF;
        const int h  = p / WW;
        const int w  = p % WW;
        float acc = s_b[co];
        #pragma unroll
        for (int dy = 0; dy < 3; ++dy) {
            const int hh = h + dy - 1;
            if ((unsigned)hh < (unsigned)HH) {
                #pragma unroll
                for (int dx = 0; dx < 3; ++dx) {
                    const int wx = w + dx - 1;
                    if ((unsigned)wx < (unsigned)WW)
                        acc += s_f[hh * WW + wx] * s_w[(dy * 3 + dx) * FF + co];
                }
            }
        }
        const float y = fmaxf(acc, 0.f);
        const int r = (h + 1) * PW + (w + 1);
        __nv_bfloat16 hi, lo;
        split_bf16(y, hi, lo);
        g_a1h[fbase + (size_t)r * FF + co] = hi;
        g_a1l[fbase + (size_t)r * FF + co] = lo;
    }
}

// ---------------------------------------------------------------------------
// Kernel 2/3: 48->48 conv as implicit GEMM via mma.sync (bf16 hi/lo, 3 pass).
// CTA = (frame, half): 450 output padded-rows. A slab (528 rows x 56ci,
// stride 112B -> conflict-free ldmatrix) loaded once; B pre-fragmented in
// m16n8k16 B-frag order (one LDS.64 per MMA operand). Warp = 16-row M tile,
// all 6 N-tiles accumulated in registers; taps = constant A-row shifts.
// PHASE 0: writes act2 hi/lo.  PHASE 1: pools ReLU outputs per (frame,half).
// FIX vs R4: PHASE-1 pooling only counts rows owned by this half
// (r - rbase < 450); tile overhang rows otherwise double-counted.
// ---------------------------------------------------------------------------
#define SLAB_ROWS 528
#define A_STRIDE  112                          // 56 bf16 per row
#define A_BYTES   (SLAB_ROWS * A_STRIDE)       // 59136
#define B_BYTES   (9 * 3 * 6 * 64 * 4)         // 41472 (162 frag groups x 64 u32)
#define OFF_AH    0
#define OFF_AL    (OFF_AH + A_BYTES)           // 59136
#define OFF_BH    (OFF_AL + A_BYTES)           // 118272
#define OFF_BL    (OFF_BH + B_BYTES)           // 159744
#define OFF_BI    (OFF_BL + B_BYTES)           // 201216
#define CONV_SMEM (OFF_BI + FF * 4)            // 201408
#define MT_TILES  29                           // ceil(450/16)
#define HALF_ROWS 450

template <int PHASE>
__global__ void __launch_bounds__(256, 1)
convmm_kernel(const __nv_bfloat16* __restrict__ inH,
              const __nv_bfloat16* __restrict__ inL,
              const float* __restrict__ w,
              const float* __restrict__ bias)
{
    extern __shared__ __align__(16) char smem[];
    __shared__ float s_pool[8 * FF];

    const int frame = blockIdx.x >> 1;
    const int half  = blockIdx.x & 1;
    const int rbase = half * HALF_ROWS;        // first output padded-row
    const int tid   = threadIdx.x;
    const int wid   = tid >> 5;
    const int lane  = tid & 31;

    float* s_bias = (float*)(smem + OFF_BI);
    if (tid < FF) s_bias[tid] = bias[tid];

    // ---- B pre-fragment fill: group = (tap*3+kc)*6+nt, slot = lane*2+reg ----
    {
        uint32_t* s_bh = (uint32_t*)(smem + OFF_BH);
        uint32_t* s_bl = (uint32_t*)(smem + OFF_BL);
        for (int i = tid; i < 162 * 64; i += 256) {
            const int group = i >> 6;
            const int slot  = i & 63;
            const int l     = slot >> 1;
            const int reg   = slot & 1;
            const int tapkc = group / 6;
            const int nt    = group - tapkc * 6;
            const int tap   = tapkc / 3;
            const int kc    = tapkc - tap * 3;
            const int n     = nt * 8 + (l >> 2);               // co
            const int k     = kc * 16 + (l & 3) * 2 + reg * 8; // ci
            const float w0 = w[(tap * FF + k)     * FF + n];
            const float w1 = w[(tap * FF + k + 1) * FF + n];
            __nv_bfloat16 h0, l0, h1, l1;
            split_bf16(w0, h0, l0);
            split_bf16(w1, h1, l1);
            s_bh[i] = (uint32_t)__bfloat16_as_ushort(h0) | ((uint32_t)__bfloat16_as_ushort(h1) << 16);
            s_bl[i] = (uint32_t)__bfloat16_as_ushort(l0) | ((uint32_t)__bfloat16_as_ushort(l1) << 16);
        }
    }

    // ---- A slab fill: slab row s = global padded row (rbase - 31 + s) ----
    {
        const uint4* srcH = (const uint4*)(inH + (size_t)frame * PROWS * FF);
        const uint4* srcL = (const uint4*)(inL + (size_t)frame * PROWS * FF);
        for (int i = tid; i < SLAB_ROWS * 7; i += 256) {
            const int s   = i / 7;
            const int blk = i - s * 7;
            const int r   = rbase - 31 + s;
            bool valid = false;
            if (r >= 0 && r < PROWS) {
                const int rd = r / PW, rm = r - rd * PW;
                valid = (rd >= 1 && rd <= HH && rm >= 1 && rm <= WW);
            }
            uint4 vh = make_uint4(0u, 0u, 0u, 0u);
            uint4 vl = make_uint4(0u, 0u, 0u, 0u);
            if (valid && blk < 6) {
                vh = srcH[(size_t)r * 6 + blk];
                vl = srcL[(size_t)r * 6 + blk];
            }
            *(uint4*)(smem + OFF_AH + s * A_STRIDE + blk * 16) = vh;
            *(uint4*)(smem + OFF_AL + s * A_STRIDE + blk * 16) = vl;
        }
    }
    __syncthreads();

    const uint32_t smb = smem_u32(smem);
    // ldmatrix per-lane fixed offset: rows 0-15 (k lo) for lanes 0-15, +16B for hi-k half
    const uint32_t laneoff = (uint32_t)((lane & 15) * A_STRIDE + ((lane >> 4) << 4));
    const uint32_t* s_bh = (const uint32_t*)(smem + OFF_BH);
    const uint32_t* s_bl = (const uint32_t*)(smem + OFF_BL);

    float pool[6][2];
    if (PHASE == 1) {
        #pragma unroll
        for (int nt = 0; nt < 6; ++nt) { pool[nt][0] = 0.f; pool[nt][1] = 0.f; }
    }

    for (int mt = wid; mt < MT_TILES; mt += 8) {
        float C[6][4];
        #pragma unroll
        for (int nt = 0; nt < 6; ++nt) {
            C[nt][0] = 0.f; C[nt][1] = 0.f; C[nt][2] = 0.f; C[nt][3] = 0.f;
        }

        const uint32_t abase_h = smb + OFF_AH + (uint32_t)((31 + mt * 16) * A_STRIDE) + laneoff;
        const uint32_t abase_l = smb + OFF_AL + (uint32_t)((31 + mt * 16) * A_STRIDE) + laneoff;

        #pragma unroll 1
        for (int tap = 0; tap < 9; ++tap) {
            const int dy = tap / 3;
            const int dr = (dy - 1) * PW + (tap - dy * 3) - 1;     // [-31, 31]
            const int aoff = dr * A_STRIDE;
            #pragma unroll
            for (int kc = 0; kc < 3; ++kc) {
                uint32_t ah[4], al[4];
                ldmx4(ah, abase_h + (uint32_t)(aoff + kc * 32));
                ldmx4(al, abase_l + (uint32_t)(aoff + kc * 32));
                const int bbase = ((tap * 3 + kc) * 6) * 64 + lane * 2;
                #pragma unroll
                for (int nt = 0; nt < 6; ++nt) {
                    const uint2 bh = *(const uint2*)(s_bh + bbase + nt * 64);
                    const uint2 bl = *(const uint2*)(s_bl + bbase + nt * 64);
                    mma_bf16(C[nt], ah, bh.x, bh.y);   // hi*hi
                    mma_bf16(C[nt], ah, bl.x, bl.y);   // hi*lo
                    mma_bf16(C[nt], al, bh.x, bh.y);   // lo*hi
                }
            }
        }

        // Epilogue: C frag (row = lane/4 (+8), col = (lane&3)*2 + {0,1})
        #pragma unroll
        for (int rh = 0; rh < 2; ++rh) {
            const int r = rbase + mt * 16 + (lane >> 2) + rh * 8;
            if (PHASE == 0) {
                if (r < PROWS) {
                    uint32_t* dH = (uint32_t*)(g_a2h + ((size_t)frame * PROWS + r) * FF);
                    uint32_t* dL = (uint32_t*)(g_a2l + ((size_t)frame * PROWS + r) * FF);
                    #pragma unroll
                    for (int nt = 0; nt < 6; ++nt) {
                        const int co = nt * 8 + (lane & 3) * 2;
                        const float y0 = fmaxf(C[nt][rh * 2]     + s_bias[co],     0.f);
                        const float y1 = fmaxf(C[nt][rh * 2 + 1] + s_bias[co + 1], 0.f);
                        __nv_bfloat16 h0, l0, h1, l1;
                        split_bf16(y0, h0, l0);
                        split_bf16(y1, h1, l1);
                        dH[co >> 1] = (uint32_t)__bfloat16_as_ushort(h0) | ((uint32_t)__bfloat16_as_ushort(h1) << 16);
                        dL[co >> 1] = (uint32_t)__bfloat16_as_ushort(l0) | ((uint32_t)__bfloat16_as_ushort(l1) << 16);
                    }
                }
            } else {
                // FIX: pool only rows OWNED by this half (tile overhang rows
                // 450..463 of half 0 are half 1's property — counting them
                // here double-counted ~13 pixels -> rel_err 4.8e-2).
                bool valid = false;
                if ((r - rbase) < HALF_ROWS && r < PROWS) {
                    const int rd = r / PW, rm = r - rd * PW;
                    valid = (rd >= 1 && rd <= HH && rm >= 1 && rm <= WW);
                }
                if (valid) {
                    #pragma unroll
                    for (int nt = 0; nt < 6; ++nt) {
                        const int co = nt * 8 + (lane & 3) * 2;
                        pool[nt][0] += fmaxf(C[nt][rh * 2]     + s_bias[co],     0.f);
                        pool[nt][1] += fmaxf(C[nt][rh * 2 + 1] + s_bias[co + 1], 0.f);
                    }
                }
            }
        }
    }

    if (PHASE == 1) {
        // Reduce across row-groups (lane>>2) via xor shuffles; lanes 0-3 hold co sums
        #pragma unroll
        for (int nt = 0; nt < 6; ++nt) {
            #pragma unroll
            for (int e = 0; e < 2; ++e) {
                float v = pool[nt][e];
                v += __shfl_xor_sync(0xffffffffu, v, 4);
                v += __shfl_xor_sync(0xffffffffu, v, 8);
                v += __shfl_xor_sync(0xffffffffu, v, 16);
                if ((lane >> 2) == 0)
                    s_pool[wid * FF + nt * 8 + lane * 2 + e] = v;
            }
        }
        __syncthreads();
        if (tid < FF) {
            float s = 0.f;
            #pragma unroll
            for (int ww = 0; ww < 8; ++ww) s += s_pool[ww * FF + tid];
            g_feats[(frame * 2 + half) * FF + tid] = s;
        }
    }
}

// ---------------------------------------------------------------------------
// Kernel 4: LSTM + BN2 + head. Single block, 256 threads, thread=(b,u).
// h exchanged via 8-lane shuffles; fast-exp gates; BN1 folded into x load.
// ---------------------------------------------------------------------------
__device__ __forceinline__ float fsig(float x)  { return __fdividef(1.f, 1.f + __expf(-x)); }
__device__ __forceinline__ float ftanh(float x) { return 1.f - __fdividef(2.f, __expf(2.f * x) + 1.f); }

__global__ void lstm_kernel(const float* __restrict__ wf,  const float* __restrict__ bf,
                            const float* __restrict__ wi1, const float* __restrict__ bi1,
                            const float* __restrict__ wi2, const float* __restrict__ bi2,
                            const float* __restrict__ wo,  const float* __restrict__ bo,
                            const float* __restrict__ bn1_g, const float* __restrict__ bn1_b,
                            const float* __restrict__ bn1_m, const float* __restrict__ bn1_v,
                            const float* __restrict__ bn2_g, const float* __restrict__ bn2_b,
                            const float* __restrict__ bn2_m, const float* __restrict__ bn2_v,
                            const float* __restrict__ w_out, const float* __restrict__ b_out,
                            float* __restrict__ out)
{
    __shared__ float s_x[BB][FF];
    __shared__ float s_w[4][FF + UU][UU];
    __shared__ float s_bias[4][UU];
    __shared__ float s_sc1[FF], s_sh1[FF];

    const int tid = threadIdx.x;
    const int b   = tid >> 3;
    const int u   = tid & 7;

    for (int i = tid; i < (FF + UU) * UU; i += 256) {
        const int r = i / UU, cu = i % UU;
        s_w[0][r][cu] = wf[i];
        s_w[1][r][cu] = wi1[i];
        s_w[2][r][cu] = wi2[i];
        s_w[3][r][cu] = wo[i];
    }
    if (tid < 4 * UU) {
        const float* bs[4] = {bf, bi1, bi2, bo};
        s_bias[tid >> 3][tid & 7] = bs[tid >> 3][tid & 7];
    }
    if (tid < FF) {
        const float sc = bn1_g[tid] * rsqrtf(bn1_v[tid] + EPSB);
        s_sc1[tid] = sc * (1.f / (float)FRAME_PIX);
        s_sh1[tid] = bn1_b[tid] - bn1_m[tid] * sc;
    }
    float c = 0.f, h = 0.f;

    const float sc2  = bn2_g[u] * rsqrtf(bn2_v[u] + EPSB);
    const float coef = sc2 * w_out[u];
    float outc = b_out[0];
    #pragma unroll
    for (int j = 0; j < UU; ++j) {
        const float s2 = bn2_g[j] * rsqrtf(bn2_v[j] + EPSB);
        outc += (bn2_b[j] - bn2_m[j] * s2) * w_out[j];
    }
    __syncthreads();

    for (int t = 0; t < TT; ++t) {
        for (int i = tid; i < BB * FF; i += 256) {
            const int bb = i / FF, co = i % FF;
            const int fr = (bb << 5) + t;
            const float ps = g_feats[(fr * 2) * FF + co] + g_feats[(fr * 2 + 1) * FF + co];
            s_x[bb][co] = ps * s_sc1[co] + s_sh1[co];
        }
        __syncthreads();

        float af = s_bias[0][u], ai = s_bias[1][u];
        float ag = s_bias[2][u], ao = s_bias[3][u];
        #pragma unroll 8
        for (int k = 0; k < FF; ++k) {
            const float xv = s_x[b][k];
            af += xv * s_w[0][k][u];
            ai += xv * s_w[1][k][u];
            ag += xv * s_w[2][k][u];
            ao += xv * s_w[3][k][u];
        }
        #pragma unroll
        for (int j = 0; j < UU; ++j) {
            const float hv = __shfl_sync(0xffffffffu, h, j, 8);
            af += hv * s_w[0][FF + j][u];
            ai += hv * s_w[1][FF + j][u];
            ag += hv * s_w[2][FF + j][u];
            ao += hv * s_w[3][FF + j][u];
        }
        c = fsig(af) * c + fsig(ai) * ftanh(ag);
        h = fsig(ao) * ftanh(c);

        float p = h * coef;
        p += __shfl_xor_sync(0xffffffffu, p, 4);
        p += __shfl_xor_sync(0xffffffffu, p, 2);
        p += __shfl_xor_sync(0xffffffffu, p, 1);
        if (u == 0) out[(b << 5) + t] = p + outc;
        __syncthreads();   // protect s_x before next overwrite
    }
}

// ---------------------------------------------------------------------------
// Launch
// ---------------------------------------------------------------------------
extern "C" void kernel_launch(void* const* d_in, const int* in_sizes, int n_in,
                              void* d_out, int out_size)
{
    const float* x     = (const float*)d_in[0];
    const float* w1    = (const float*)d_in[1];
    const float* b1    = (const float*)d_in[2];
    const float* w2    = (const float*)d_in[3];
    const float* b2    = (const float*)d_in[4];
    const float* w3    = (const float*)d_in[5];
    const float* b3    = (const float*)d_in[6];
    const float* bn1_g = (const float*)d_in[7];
    const float* bn1_b = (const float*)d_in[8];
    const float* bn1_m = (const float*)d_in[9];
    const float* bn1_v = (const float*)d_in[10];
    const float* wf    = (const float*)d_in[11];
    const float* bf    = (const float*)d_in[12];
    const float* wi1   = (const float*)d_in[13];
    const float* bi1   = (const float*)d_in[14];
    const float* wi2   = (const float*)d_in[15];
    const float* bi2   = (const float*)d_in[16];
    const float* wo    = (const float*)d_in[17];
    const float* bo    = (const float*)d_in[18];
    const float* bn2_g = (const float*)d_in[19];
    const float* bn2_b = (const float*)d_in[20];
    const float* bn2_m = (const float*)d_in[21];
    const float* bn2_v = (const float*)d_in[22];
    const float* w_out = (const float*)d_in[23];
    const float* b_out = (const float*)d_in[24];
    float* out = (float*)d_out;

    cudaFuncSetAttribute(convmm_kernel<0>, cudaFuncAttributeMaxDynamicSharedMemorySize, CONV_SMEM);
    cudaFuncSetAttribute(convmm_kernel<1>, cudaFuncAttributeMaxDynamicSharedMemorySize, CONV_SMEM);

    __nv_bfloat16 *a1h = nullptr, *a1l = nullptr, *a2h = nullptr, *a2l = nullptr;
    cudaGetSymbolAddress((void**)&a1h, g_a1h);
    cudaGetSymbolAddress((void**)&a1l, g_a1l);
    cudaGetSymbolAddress((void**)&a2h, g_a2h);
    cudaGetSymbolAddress((void**)&a2l, g_a2l);

    conv1_kernel<<<NFRAMES, 256>>>(x, w1, b1);
    convmm_kernel<0><<<NFRAMES * 2, 256, CONV_SMEM>>>(a1h, a1l, w2, b2);
    convmm_kernel<1><<<NFRAMES * 2, 256, CONV_SMEM>>>(a2h, a2l, w3, b3);
    lstm_kernel<<<1, 256>>>(wf, bf, wi1, bi1, wi2, bi2, wo, bo,
                            bn1_g, bn1_b, bn1_m, bn1_v,
                            bn2_g, bn2_b, bn2_m, bn2_v,
                            w_out, b_out, out);
}

// round 6
// speedup vs baseline: 1.9826x; 1.1000x over previous
#include <cuda_runtime.h>
#include <cuda_bf16.h>
#include <cstdint>
#include <math.h>

// Problem constants
#define BB   32
#define TT   32
#define HH   28
#define WW   28
#define FF   48
#define UU   8
#define EPSB 1e-3f
#define NFRAMES (BB*TT)            // 1024
#define FRAME_PIX (HH*WW)          // 784
#define PW   30                    // padded width
#define PROWS (PW*PW)              // 900 padded pixel-rows per frame

// ---------------------------------------------------------------------------
// Warp-MMA helpers (baseline sm_80+ ISA)
// ---------------------------------------------------------------------------
__device__ __forceinline__ uint32_t smem_u32(const void* p) {
    return (uint32_t)__cvta_generic_to_shared(p);
}
__device__ __forceinline__ void ldmx4(uint32_t a[4], uint32_t addr) {
    asm volatile("ldmatrix.sync.aligned.m8n8.x4.shared.b16 {%0,%1,%2,%3}, [%4];"
                 : "=r"(a[0]), "=r"(a[1]), "=r"(a[2]), "=r"(a[3]) : "r"(addr));
}
__device__ __forceinline__ void mma_bf16(float c[4], const uint32_t a[4],
                                         uint32_t b0, uint32_t b1) {
    asm volatile("mma.sync.aligned.m16n8k16.row.col.f32.bf16.bf16.f32 "
                 "{%0,%1,%2,%3},{%4,%5,%6,%7},{%8,%9},{%0,%1,%2,%3};"
                 : "+f"(c[0]), "+f"(c[1]), "+f"(c[2]), "+f"(c[3])
                 : "r"(a[0]), "r"(a[1]), "r"(a[2]), "r"(a[3]), "r"(b0), "r"(b1));
}
__device__ __forceinline__ void split_bf16(float y, __nv_bfloat16& hi, __nv_bfloat16& lo) {
    hi = __float2bfloat16_rn(y);
    lo = __float2bfloat16_rn(y - __bfloat162float(hi));
}

// ---------------------------------------------------------------------------
// Scratch: hi/lo bf16 activations, dense [frame][900 padded rows][48]
// ---------------------------------------------------------------------------
__device__ __align__(16) __nv_bfloat16 g_a1h[NFRAMES * PROWS * FF];
__device__ __align__(16) __nv_bfloat16 g_a1l[NFRAMES * PROWS * FF];
__device__ __align__(16) __nv_bfloat16 g_a2h[NFRAMES * PROWS * FF];
__device__ __align__(16) __nv_bfloat16 g_a2l[NFRAMES * PROWS * FF];
__device__ float g_feats[NFRAMES * 2 * FF];   // per-(frame,half) pooled partials

// ---------------------------------------------------------------------------
// Kernel 1: conv1 (C=1 -> 48) + ReLU, direct fp32; writes hi/lo bf16 split.
// ---------------------------------------------------------------------------
__global__ void conv1_kernel(const float* __restrict__ x,
                             const float* __restrict__ w1,
                             const float* __restrict__ b1)
{
    __shared__ float s_f[FRAME_PIX];
    __shared__ float s_w[9 * FF];
    __shared__ float s_b[FF];

    const int frame = blockIdx.x;
    const int tid   = threadIdx.x;

    for (int i = tid; i < FRAME_PIX; i += 256) s_f[i] = x[frame * FRAME_PIX + i];
    for (int i = tid; i < 9 * FF;   i += 256) s_w[i] = w1[i];
    if (tid < FF) s_b[tid] = b1[tid];
    __syncthreads();

    const size_t fbase = (size_t)frame * PROWS * FF;
    for (int idx = tid; idx < FRAME_PIX * FF; idx += 256) {
        const int co = idx % FF;
        const int p  = idx / FF;
        const int h  = p / WW;
        const int w  = p % WW;
        float acc = s_b[co];
        #pragma unroll
        for (int dy = 0; dy < 3; ++dy) {
            const int hh = h + dy - 1;
            if ((unsigned)hh < (unsigned)HH) {
                #pragma unroll
                for (int dx = 0; dx < 3; ++dx) {
                    const int wx = w + dx - 1;
                    if ((unsigned)wx < (unsigned)WW)
                        acc += s_f[hh * WW + wx] * s_w[(dy * 3 + dx) * FF + co];
                }
            }
        }
        const float y = fmaxf(acc, 0.f);
        const int r = (h + 1) * PW + (w + 1);
        __nv_bfloat16 hi, lo;
        split_bf16(y, hi, lo);
        g_a1h[fbase + (size_t)r * FF + co] = hi;
        g_a1l[fbase + (size_t)r * FF + co] = lo;
    }
}

// ---------------------------------------------------------------------------
// Kernel 2/3: 48->48 conv via mma.sync, bf16 hi/lo 3-pass.
// R6 restructure: tapkc OUTER loop with B fragments hoisted to registers,
// 4 M-tiles per warp resident in C regs -> B smem traffic cut 4x
// (was the binding resource). Slab padded to 576 zero-filled rows so the
// fixed 4-tile schedule needs no guards; overhang tiles masked at epilogue.
// ---------------------------------------------------------------------------
#define SLAB_ROWS 576
#define A_STRIDE  112                          // 56 bf16 per row
#define A_BYTES   (SLAB_ROWS * A_STRIDE)       // 64512
#define B_BYTES   (9 * 3 * 6 * 64 * 4)         // 41472
#define OFF_AH    0
#define OFF_AL    (OFF_AH + A_BYTES)           // 64512
#define OFF_BH    (OFF_AL + A_BYTES)           // 129024
#define OFF_BL    (OFF_BH + B_BYTES)           // 170496
#define OFF_BI    (OFF_BL + B_BYTES)           // 211968
#define CONV_SMEM (OFF_BI + FF * 4)            // 212160
#define MT_TILES  29                           // ceil(450/16)
#define HALF_ROWS 450
#define T_PER_W   4                            // M-tiles per warp (8 warps x 4 = 32)

template <int PHASE>
__global__ void __launch_bounds__(256, 1)
convmm_kernel(const __nv_bfloat16* __restrict__ inH,
              const __nv_bfloat16* __restrict__ inL,
              const float* __restrict__ w,
              const float* __restrict__ bias)
{
    extern __shared__ __align__(16) char smem[];
    __shared__ float s_pool[8 * FF];

    const int frame = blockIdx.x >> 1;
    const int half  = blockIdx.x & 1;
    const int rbase = half * HALF_ROWS;
    const int tid   = threadIdx.x;
    const int wid   = tid >> 5;
    const int lane  = tid & 31;

    float* s_bias = (float*)(smem + OFF_BI);
    if (tid < FF) s_bias[tid] = bias[tid];

    // ---- B pre-fragment fill: group = (tap*3+kc)*6+nt, slot = lane*2+reg ----
    {
        uint32_t* s_bh = (uint32_t*)(smem + OFF_BH);
        uint32_t* s_bl = (uint32_t*)(smem + OFF_BL);
        for (int i = tid; i < 162 * 64; i += 256) {
            const int group = i >> 6;
            const int slot  = i & 63;
            const int l     = slot >> 1;
            const int reg   = slot & 1;
            const int tapkc = group / 6;
            const int nt    = group - tapkc * 6;
            const int tap   = tapkc / 3;
            const int kc    = tapkc - tap * 3;
            const int n     = nt * 8 + (l >> 2);               // co
            const int k     = kc * 16 + (l & 3) * 2 + reg * 8; // ci
            const float w0 = w[(tap * FF + k)     * FF + n];
            const float w1 = w[(tap * FF + k + 1) * FF + n];
            __nv_bfloat16 h0, l0, h1, l1;
            split_bf16(w0, h0, l0);
            split_bf16(w1, h1, l1);
            s_bh[i] = (uint32_t)__bfloat16_as_ushort(h0) | ((uint32_t)__bfloat16_as_ushort(h1) << 16);
            s_bl[i] = (uint32_t)__bfloat16_as_ushort(l0) | ((uint32_t)__bfloat16_as_ushort(l1) << 16);
        }
    }

    // ---- A slab fill: slab row s = global padded row (rbase - 31 + s) ----
    {
        const uint4* srcH = (const uint4*)(inH + (size_t)frame * PROWS * FF);
        const uint4* srcL = (const uint4*)(inL + (size_t)frame * PROWS * FF);
        for (int i = tid; i < SLAB_ROWS * 7; i += 256) {
            const int s   = i / 7;
            const int blk = i - s * 7;
            const int r   = rbase - 31 + s;
            bool valid = false;
            if (r >= 0 && r < PROWS) {
                const int rd = r / PW, rm = r - rd * PW;
                valid = (rd >= 1 && rd <= HH && rm >= 1 && rm <= WW);
            }
            uint4 vh = make_uint4(0u, 0u, 0u, 0u);
            uint4 vl = make_uint4(0u, 0u, 0u, 0u);
            if (valid && blk < 6) {
                vh = srcH[(size_t)r * 6 + blk];
                vl = srcL[(size_t)r * 6 + blk];
            }
            *(uint4*)(smem + OFF_AH + s * A_STRIDE + blk * 16) = vh;
            *(uint4*)(smem + OFF_AL + s * A_STRIDE + blk * 16) = vl;
        }
    }
    __syncthreads();

    const uint32_t smb = smem_u32(smem);
    const uint32_t laneoff = (uint32_t)((lane & 15) * A_STRIDE + ((lane >> 4) << 4));
    const uint32_t* s_bh = (const uint32_t*)(smem + OFF_BH);
    const uint32_t* s_bl = (const uint32_t*)(smem + OFF_BL);

    // Per-warp tile bases (tiles wid, wid+8, wid+16, wid+24)
    uint32_t abase_h[T_PER_W], abase_l[T_PER_W];
    #pragma unroll
    for (int i = 0; i < T_PER_W; ++i) {
        const int mt = wid + 8 * i;
        abase_h[i] = smb + OFF_AH + (uint32_t)((31 + mt * 16) * A_STRIDE) + laneoff;
        abase_l[i] = smb + OFF_AL + (uint32_t)((31 + mt * 16) * A_STRIDE) + laneoff;
    }

    float C[T_PER_W][6][4];
    #pragma unroll
    for (int i = 0; i < T_PER_W; ++i)
        #pragma unroll
        for (int nt = 0; nt < 6; ++nt) {
            C[i][nt][0] = 0.f; C[i][nt][1] = 0.f; C[i][nt][2] = 0.f; C[i][nt][3] = 0.f;
        }

    #pragma unroll 1
    for (int tap = 0; tap < 9; ++tap) {
        const int dy = tap / 3;
        const int dr = (dy - 1) * PW + (tap - dy * 3) - 1;     // [-31, 31]
        const int aoff = dr * A_STRIDE;
        #pragma unroll
        for (int kc = 0; kc < 3; ++kc) {
            // B fragments for this (tap,kc) — register-resident, reused by 4 tiles
            uint2 BH[6], BL[6];
            const int bbase = ((tap * 3 + kc) * 6) * 64 + lane * 2;
            #pragma unroll
            for (int nt = 0; nt < 6; ++nt) {
                BH[nt] = *(const uint2*)(s_bh + bbase + nt * 64);
                BL[nt] = *(const uint2*)(s_bl + bbase + nt * 64);
            }
            #pragma unroll
            for (int i = 0; i < T_PER_W; ++i) {
                uint32_t ah[4], al[4];
                ldmx4(ah, abase_h[i] + (uint32_t)(aoff + kc * 32));
                ldmx4(al, abase_l[i] + (uint32_t)(aoff + kc * 32));
                #pragma unroll
                for (int nt = 0; nt < 6; ++nt) {
                    mma_bf16(C[i][nt], ah, BH[nt].x, BH[nt].y);   // hi*hi
                    mma_bf16(C[i][nt], ah, BL[nt].x, BL[nt].y);   // hi*lo
                    mma_bf16(C[i][nt], al, BH[nt].x, BH[nt].y);   // lo*hi
                }
            }
        }
    }

    // ---- Epilogue ----
    float pool[6][2];
    if (PHASE == 1) {
        #pragma unroll
        for (int nt = 0; nt < 6; ++nt) { pool[nt][0] = 0.f; pool[nt][1] = 0.f; }
    }

    #pragma unroll
    for (int i = 0; i < T_PER_W; ++i) {
        const int mt = wid + 8 * i;
        if (mt >= MT_TILES && PHASE == 1) continue;    // overhang tiles: pool-skip
        #pragma unroll
        for (int rh = 0; rh < 2; ++rh) {
            const int r = rbase + mt * 16 + (lane >> 2) + rh * 8;
            if (PHASE == 0) {
                if (r < PROWS) {
                    uint32_t* dH = (uint32_t*)(g_a2h + ((size_t)frame * PROWS + r) * FF);
                    uint32_t* dL = (uint32_t*)(g_a2l + ((size_t)frame * PROWS + r) * FF);
                    #pragma unroll
                    for (int nt = 0; nt < 6; ++nt) {
                        const int co = nt * 8 + (lane & 3) * 2;
                        const float y0 = fmaxf(C[i][nt][rh * 2]     + s_bias[co],     0.f);
                        const float y1 = fmaxf(C[i][nt][rh * 2 + 1] + s_bias[co + 1], 0.f);
                        __nv_bfloat16 h0, l0, h1, l1;
                        split_bf16(y0, h0, l0);
                        split_bf16(y1, h1, l1);
                        dH[co >> 1] = (uint32_t)__bfloat16_as_ushort(h0) | ((uint32_t)__bfloat16_as_ushort(h1) << 16);
                        dL[co >> 1] = (uint32_t)__bfloat16_as_ushort(l0) | ((uint32_t)__bfloat16_as_ushort(l1) << 16);
                    }
                }
            } else {
                bool valid = false;
                if ((r - rbase) < HALF_ROWS && r < PROWS) {
                    const int rd = r / PW, rm = r - rd * PW;
                    valid = (rd >= 1 && rd <= HH && rm >= 1 && rm <= WW);
                }
                if (valid) {
                    #pragma unroll
                    for (int nt = 0; nt < 6; ++nt) {
                        const int co = nt * 8 + (lane & 3) * 2;
                        pool[nt][0] += fmaxf(C[i][nt][rh * 2]     + s_bias[co],     0.f);
                        pool[nt][1] += fmaxf(C[i][nt][rh * 2 + 1] + s_bias[co + 1], 0.f);
                    }
                }
            }
        }
    }

    if (PHASE == 1) {
        #pragma unroll
        for (int nt = 0; nt < 6; ++nt) {
            #pragma unroll
            for (int e = 0; e < 2; ++e) {
                float v = pool[nt][e];
                v += __shfl_xor_sync(0xffffffffu, v, 4);
                v += __shfl_xor_sync(0xffffffffu, v, 8);
                v += __shfl_xor_sync(0xffffffffu, v, 16);
                if ((lane >> 2) == 0)
                    s_pool[wid * FF + nt * 8 + lane * 2 + e] = v;
            }
        }
        __syncthreads();
        if (tid < FF) {
            float s = 0.f;
            #pragma unroll
            for (int ww = 0; ww < 8; ++ww) s += s_pool[ww * FF + tid];
            g_feats[(frame * 2 + half) * FF + tid] = s;
        }
    }
}

// ---------------------------------------------------------------------------
// Kernel 4: LSTM + BN2 + head. R6: one block (1 warp) per batch element —
// batch is parallel, only t is sequential. Weight column in registers,
// x pre-staged in smem, gates/h via shuffles, (c,h) replicated in all lanes.
// ---------------------------------------------------------------------------
__device__ __forceinline__ float fsig(float x)  { return __fdividef(1.f, 1.f + __expf(-x)); }
__device__ __forceinline__ float ftanh(float x) { return 1.f - __fdividef(2.f, __expf(2.f * x) + 1.f); }

__global__ void __launch_bounds__(32, 1)
lstm_kernel(const float* __restrict__ wf,  const float* __restrict__ bf,
            const float* __restrict__ wi1, const float* __restrict__ bi1,
            const float* __restrict__ wi2, const float* __restrict__ bi2,
            const float* __restrict__ wo,  const float* __restrict__ bo,
            const float* __restrict__ bn1_g, const float* __restrict__ bn1_b,
            const float* __restrict__ bn1_m, const float* __restrict__ bn1_v,
            const float* __restrict__ bn2_g, const float* __restrict__ bn2_b,
            const float* __restrict__ bn2_m, const float* __restrict__ bn2_v,
            const float* __restrict__ w_out, const float* __restrict__ b_out,
            float* __restrict__ out)
{
    __shared__ float s_x[TT][FF];
    __shared__ float s_sc1[FF], s_sh1[FF];

    const int b    = blockIdx.x;
    const int lane = threadIdx.x;
    const int u    = lane & 7;

    // weight column for this lane's (gate, u)
    const float* Wg = (lane < 8) ? wf : (lane < 16) ? wi1 : (lane < 24) ? wi2 : wo;
    const float* Bg = (lane < 8) ? bf : (lane < 16) ? bi1 : (lane < 24) ? bi2 : bo;
    float wcol[FF + UU];
    #pragma unroll
    for (int k = 0; k < FF + UU; ++k) wcol[k] = Wg[k * UU + u];
    const float bgate = Bg[u];

    // BN1 fold (+1/784 mean)
    for (int co = lane; co < FF; co += 32) {
        const float sc = bn1_g[co] * rsqrtf(bn1_v[co] + EPSB);
        s_sc1[co] = sc * (1.f / (float)FRAME_PIX);
        s_sh1[co] = bn1_b[co] - bn1_m[co] * sc;
    }
    __syncwarp();

    // Pre-stage normalized features for all T
    for (int i = lane; i < TT * FF; i += 32) {
        const int t = i / FF, co = i - t * FF;
        const int fr = (b << 5) + t;
        const float ps = g_feats[(fr * 2) * FF + co] + g_feats[(fr * 2 + 1) * FF + co];
        s_x[t][co] = ps * s_sc1[co] + s_sh1[co];
    }
    __syncwarp();

    // BN2 + head fold
    const float sc2  = bn2_g[u] * rsqrtf(bn2_v[u] + EPSB);
    const float coef = sc2 * w_out[u];
    float outc = b_out[0];
    #pragma unroll
    for (int j = 0; j < UU; ++j) {
        const float s2 = bn2_g[j] * rsqrtf(bn2_v[j] + EPSB);
        outc += (bn2_b[j] - bn2_m[j] * s2) * w_out[j];
    }

    float c = 0.f, h = 0.f;   // replicated: every lane holds state for its u

    for (int t = 0; t < TT; ++t) {
        float a = bgate;
        #pragma unroll
        for (int k = 0; k < FF; ++k) a += s_x[t][k] * wcol[k];   // broadcast LDS
        #pragma unroll
        for (int j = 0; j < UU; ++j)
            a += __shfl_sync(0xffffffffu, h, j) * wcol[FF + j];

        const float fg = fsig (__shfl_sync(0xffffffffu, a, u));
        const float ig = fsig (__shfl_sync(0xffffffffu, a, u + 8));
        const float gg = ftanh(__shfl_sync(0xffffffffu, a, u + 16));
        const float og = fsig (__shfl_sync(0xffffffffu, a, u + 24));
        c = fg * c + ig * gg;
        h = og * ftanh(c);

        float p = h * coef;
        p += __shfl_xor_sync(0xffffffffu, p, 1);
        p += __shfl_xor_sync(0xffffffffu, p, 2);
        p += __shfl_xor_sync(0xffffffffu, p, 4);
        if (lane == 0) out[(b << 5) + t] = p + outc;
    }
}

// ---------------------------------------------------------------------------
// Launch
// ---------------------------------------------------------------------------
extern "C" void kernel_launch(void* const* d_in, const int* in_sizes, int n_in,
                              void* d_out, int out_size)
{
    const float* x     = (const float*)d_in[0];
    const float* w1    = (const float*)d_in[1];
    const float* b1    = (const float*)d_in[2];
    const float* w2    = (const float*)d_in[3];
    const float* b2    = (const float*)d_in[4];
    const float* w3    = (const float*)d_in[5];
    const float* b3    = (const float*)d_in[6];
    const float* bn1_g = (const float*)d_in[7];
    const float* bn1_b = (const float*)d_in[8];
    const float* bn1_m = (const float*)d_in[9];
    const float* bn1_v = (const float*)d_in[10];
    const float* wf    = (const float*)d_in[11];
    const float* bf    = (const float*)d_in[12];
    const float* wi1   = (const float*)d_in[13];
    const float* bi1   = (const float*)d_in[14];
    const float* wi2   = (const float*)d_in[15];
    const float* bi2   = (const float*)d_in[16];
    const float* wo    = (const float*)d_in[17];
    const float* bo    = (const float*)d_in[18];
    const float* bn2_g = (const float*)d_in[19];
    const float* bn2_b = (const float*)d_in[20];
    const float* bn2_m = (const float*)d_in[21];
    const float* bn2_v = (const float*)d_in[22];
    const float* w_out = (const float*)d_in[23];
    const float* b_out = (const float*)d_in[24];
    float* out = (float*)d_out;

    cudaFuncSetAttribute(convmm_kernel<0>, cudaFuncAttributeMaxDynamicSharedMemorySize, CONV_SMEM);
    cudaFuncSetAttribute(convmm_kernel<1>, cudaFuncAttributeMaxDynamicSharedMemorySize, CONV_SMEM);

    __nv_bfloat16 *a1h = nullptr, *a1l = nullptr, *a2h = nullptr, *a2l = nullptr;
    cudaGetSymbolAddress((void**)&a1h, g_a1h);
    cudaGetSymbolAddress((void**)&a1l, g_a1l);
    cudaGetSymbolAddress((void**)&a2h, g_a2h);
    cudaGetSymbolAddress((void**)&a2l, g_a2l);

    conv1_kernel<<<NFRAMES, 256>>>(x, w1, b1);
    convmm_kernel<0><<<NFRAMES * 2, 256, CONV_SMEM>>>(a1h, a1l, w2, b2);
    convmm_kernel<1><<<NFRAMES * 2, 256, CONV_SMEM>>>(a2h, a2l, w3, b3);
    lstm_kernel<<<BB, 32>>>(wf, bf, wi1, bi1, wi2, bi2, wo, bo,
                            bn1_g, bn1_b, bn1_m, bn1_v,
                            bn2_g, bn2_b, bn2_m, bn2_v,
                            w_out, b_out, out);
}

// round 7
// speedup vs baseline: 3.3005x; 1.6648x over previous
#include <cuda_runtime.h>
#include <cuda_fp16.h>
#include <cstdint>
#include <math.h>

// Problem constants
#define BB   32
#define TT   32
#define HH   28
#define WW   28
#define FF   48
#define UU   8
#define EPSB 1e-3f
#define NFRAMES (BB*TT)            // 1024
#define FRAME_PIX (HH*WW)          // 784
#define PW   30                    // padded width
#define PROWS (PW*PW)              // 900 padded pixel-rows per frame

// ---------------------------------------------------------------------------
// Warp-MMA helpers
// ---------------------------------------------------------------------------
__device__ __forceinline__ uint32_t smem_u32(const void* p) {
    return (uint32_t)__cvta_generic_to_shared(p);
}
__device__ __forceinline__ void ldmx4(uint32_t a[4], uint32_t addr) {
    asm volatile("ldmatrix.sync.aligned.m8n8.x4.shared.b16 {%0,%1,%2,%3}, [%4];"
                 : "=r"(a[0]), "=r"(a[1]), "=r"(a[2]), "=r"(a[3]) : "r"(addr));
}
__device__ __forceinline__ void mma_fp16(float c[4], const uint32_t a[4],
                                         uint32_t b0, uint32_t b1) {
    asm volatile("mma.sync.aligned.m16n8k16.row.col.f32.f16.f16.f32 "
                 "{%0,%1,%2,%3},{%4,%5,%6,%7},{%8,%9},{%0,%1,%2,%3};"
                 : "+f"(c[0]), "+f"(c[1]), "+f"(c[2]), "+f"(c[3])
                 : "r"(a[0]), "r"(a[1]), "r"(a[2]), "r"(a[3]), "r"(b0), "r"(b1));
}
__device__ __forceinline__ void split_fp16(float y, __half& hi, __half& lo) {
    hi = __float2half_rn(y);
    lo = __float2half_rn(y - __half2float(hi));
}
__device__ __forceinline__ void cpa16(uint32_t dst, const void* src, uint32_t srcbytes) {
    asm volatile("cp.async.cg.shared.global [%0], [%1], 16, %2;"
                 :: "r"(dst), "l"(src), "r"(srcbytes));
}
__device__ __forceinline__ void cpa_wait_all() {
    asm volatile("cp.async.commit_group;\n\tcp.async.wait_group 0;" ::: "memory");
}

// ---------------------------------------------------------------------------
// Scratch: hi/lo fp16 activations [frame][900 padded rows][48]; prebuilt B frags
// ---------------------------------------------------------------------------
__device__ __align__(16) __half g_a1h[NFRAMES * PROWS * FF];
__device__ __align__(16) __half g_a1l[NFRAMES * PROWS * FF];
__device__ __align__(16) __half g_a2h[NFRAMES * PROWS * FF];
__device__ __align__(16) __half g_a2l[NFRAMES * PROWS * FF];
__device__ __align__(16) uint32_t g_bfrag[2][27 * 6 * 64];  // fp16x2 fragments
__device__ float g_feats[NFRAMES * 2 * FF];

// ---------------------------------------------------------------------------
// Kernel 0: pre-fragment conv weights (identical for all CTAs; built once/run)
// group = (tap*3+kc)*6+nt, slot = lane*2+reg
// ---------------------------------------------------------------------------
__global__ void prep_kernel(const float* __restrict__ w2,
                            const float* __restrict__ w3)
{
    const float* w = (blockIdx.x == 0) ? w2 : w3;
    uint32_t* dst = g_bfrag[blockIdx.x];
    for (int i = threadIdx.x; i < 162 * 64; i += 256) {
        const int group = i >> 6;
        const int slot  = i & 63;
        const int l     = slot >> 1;
        const int reg   = slot & 1;
        const int tapkc = group / 6;
        const int nt    = group - tapkc * 6;
        const int tap   = tapkc / 3;
        const int kc    = tapkc - tap * 3;
        const int n     = nt * 8 + (l >> 2);               // co
        const int k     = kc * 16 + (l & 3) * 2 + reg * 8; // ci
        const __half h0 = __float2half_rn(w[(tap * FF + k)     * FF + n]);
        const __half h1 = __float2half_rn(w[(tap * FF + k + 1) * FF + n]);
        dst[i] = (uint32_t)__half_as_ushort(h0) | ((uint32_t)__half_as_ushort(h1) << 16);
    }
}

// ---------------------------------------------------------------------------
// Kernel 1: conv1 (C=1 -> 48) + ReLU, direct fp32; writes hi/lo fp16 split.
// ---------------------------------------------------------------------------
__global__ void conv1_kernel(const float* __restrict__ x,
                             const float* __restrict__ w1,
                             const float* __restrict__ b1)
{
    __shared__ float s_f[FRAME_PIX];
    __shared__ float s_w[9 * FF];
    __shared__ float s_b[FF];

    const int frame = blockIdx.x;
    const int tid   = threadIdx.x;

    for (int i = tid; i < FRAME_PIX; i += 256) s_f[i] = x[frame * FRAME_PIX + i];
    for (int i = tid; i < 9 * FF;   i += 256) s_w[i] = w1[i];
    if (tid < FF) s_b[tid] = b1[tid];
    __syncthreads();

    const size_t fbase = (size_t)frame * PROWS * FF;
    for (int idx = tid; idx < FRAME_PIX * FF; idx += 256) {
        const int co = idx % FF;
        const int p  = idx / FF;
        const int h  = p / WW;
        const int w  = p % WW;
        float acc = s_b[co];
        #pragma unroll
        for (int dy = 0; dy < 3; ++dy) {
            const int hh = h + dy - 1;
            if ((unsigned)hh < (unsigned)HH) {
                #pragma unroll
                for (int dx = 0; dx < 3; ++dx) {
                    const int wx = w + dx - 1;
                    if ((unsigned)wx < (unsigned)WW)
                        acc += s_f[hh * WW + wx] * s_w[(dy * 3 + dx) * FF + co];
                }
            }
        }
        const float y = fmaxf(acc, 0.f);
        const int r = (h + 1) * PW + (w + 1);
        __half hi, lo;
        split_fp16(y, hi, lo);
        g_a1h[fbase + (size_t)r * FF + co] = hi;
        g_a1l[fbase + (size_t)r * FF + co] = lo;
    }
}

// ---------------------------------------------------------------------------
// Kernel 2/3: 48->48 conv via mma.sync, fp16 2-pass (A split hi/lo, W single).
// CTA = (frame, half). A slab 544 rows x 112B (conflict-free ldmatrix),
// filled via cp.async with zero-fill halo. B fragments cp.async'd from the
// prebuilt global array. Warp = 4 M-tiles (clamped to 28; dups skipped),
// B frags register-hoisted, 12 MMAs per (tapkc, tile).
// ---------------------------------------------------------------------------
#define SLAB_ROWS 544
#define A_STRIDE  112                          // 48 fp16 data + 8 pad
#define A_BYTES   (SLAB_ROWS * A_STRIDE)       // 60928
#define B_BYTES   (27 * 6 * 64 * 4)            // 41472
#define OFF_AH    0
#define OFF_AL    (OFF_AH + A_BYTES)           // 60928
#define OFF_B     (OFF_AL + A_BYTES)           // 121856
#define OFF_BI    (OFF_B + B_BYTES)            // 163328
#define CONV_SMEM (OFF_BI + FF * 4)            // 163520
#define MT_TILES  29
#define HALF_ROWS 450
#define T_PER_W   4

template <int PHASE>
__global__ void __launch_bounds__(256, 1)
convmm_kernel(const __half* __restrict__ inH,
              const __half* __restrict__ inL,
              const uint32_t* __restrict__ bfrag,
              const float* __restrict__ bias)
{
    extern __shared__ __align__(16) char smem[];
    __shared__ float s_pool[8 * FF];

    const int frame = blockIdx.x >> 1;
    const int half  = blockIdx.x & 1;
    const int rbase = half * HALF_ROWS;
    const int tid   = threadIdx.x;
    const int wid   = tid >> 5;
    const int lane  = tid & 31;
    const uint32_t smb = smem_u32(smem);

    float* s_bias = (float*)(smem + OFF_BI);
    if (tid < FF) s_bias[tid] = bias[tid];

    // ---- B fragments: straight 16B async copies from prebuilt global ----
    for (int i = tid; i < B_BYTES / 16; i += 256)
        cpa16(smb + OFF_B + i * 16, (const char*)bfrag + i * 16, 16);

    // ---- A slab via cp.async, zero-fill for halo/padding ----
    {
        const char* srcH = (const char*)(inH + (size_t)frame * PROWS * FF);
        const char* srcL = (const char*)(inL + (size_t)frame * PROWS * FF);
        for (int i = tid; i < SLAB_ROWS * 7; i += 256) {
            const int s   = i / 7;
            const int blk = i - s * 7;
            const int r   = rbase - 31 + s;
            bool valid = false;
            if (r >= 0 && r < PROWS && blk < 6) {
                const int rd = r / PW, rm = r - rd * PW;
                valid = (rd >= 1 && rd <= HH && rm >= 1 && rm <= WW);
            }
            const long off = valid ? ((long)r * 96 + blk * 16) : 0;
            const uint32_t n = valid ? 16u : 0u;
            cpa16(smb + OFF_AH + s * A_STRIDE + blk * 16, srcH + off, n);
            cpa16(smb + OFF_AL + s * A_STRIDE + blk * 16, srcL + off, n);
        }
    }
    cpa_wait_all();
    __syncthreads();

    const uint32_t laneoff = (uint32_t)((lane & 15) * A_STRIDE + ((lane >> 4) << 4));
    const uint32_t* s_b = (const uint32_t*)(smem + OFF_B);

    // Per-warp tiles (clamped; duplicates discarded at epilogue)
    int mtv[T_PER_W];
    uint32_t abase_h[T_PER_W], abase_l[T_PER_W];
    #pragma unroll
    for (int i = 0; i < T_PER_W; ++i) {
        int mt = wid + 8 * i;
        mtv[i] = mt;
        if (mt > 28) mt = 28;
        abase_h[i] = smb + OFF_AH + (uint32_t)((31 + mt * 16) * A_STRIDE) + laneoff;
        abase_l[i] = smb + OFF_AL + (uint32_t)((31 + mt * 16) * A_STRIDE) + laneoff;
    }

    float C[T_PER_W][6][4];
    #pragma unroll
    for (int i = 0; i < T_PER_W; ++i)
        #pragma unroll
        for (int nt = 0; nt < 6; ++nt) {
            C[i][nt][0] = 0.f; C[i][nt][1] = 0.f; C[i][nt][2] = 0.f; C[i][nt][3] = 0.f;
        }

    #pragma unroll 1
    for (int tap = 0; tap < 9; ++tap) {
        const int dy = tap / 3;
        const int aoff = ((dy - 1) * PW + (tap - dy * 3) - 1) * A_STRIDE;
        #pragma unroll
        for (int kc = 0; kc < 3; ++kc) {
            uint2 BW[6];
            const int bbase = ((tap * 3 + kc) * 6) * 64 + lane * 2;
            #pragma unroll
            for (int nt = 0; nt < 6; ++nt)
                BW[nt] = *(const uint2*)(s_b + bbase + nt * 64);
            #pragma unroll
            for (int i = 0; i < T_PER_W; ++i) {
                uint32_t ah[4], al[4];
                ldmx4(ah, abase_h[i] + (uint32_t)(aoff + kc * 32));
                ldmx4(al, abase_l[i] + (uint32_t)(aoff + kc * 32));
                #pragma unroll
                for (int nt = 0; nt < 6; ++nt) {
                    mma_fp16(C[i][nt], ah, BW[nt].x, BW[nt].y);   // hi * w
                    mma_fp16(C[i][nt], al, BW[nt].x, BW[nt].y);   // lo * w
                }
            }
        }
    }

    // ---- Epilogue ----
    float pool[6][2];
    if (PHASE == 1) {
        #pragma unroll
        for (int nt = 0; nt < 6; ++nt) { pool[nt][0] = 0.f; pool[nt][1] = 0.f; }
    }

    #pragma unroll
    for (int i = 0; i < T_PER_W; ++i) {
        if (mtv[i] > 28) continue;     // clamped duplicate tile
        #pragma unroll
        for (int rh = 0; rh < 2; ++rh) {
            const int r = rbase + mtv[i] * 16 + (lane >> 2) + rh * 8;
            if (PHASE == 0) {
                if (r < PROWS) {
                    uint32_t* dH = (uint32_t*)(g_a2h + ((size_t)frame * PROWS + r) * FF);
                    uint32_t* dL = (uint32_t*)(g_a2l + ((size_t)frame * PROWS + r) * FF);
                    #pragma unroll
                    for (int nt = 0; nt < 6; ++nt) {
                        const int co = nt * 8 + (lane & 3) * 2;
                        const float y0 = fmaxf(C[i][nt][rh * 2]     + s_bias[co],     0.f);
                        const float y1 = fmaxf(C[i][nt][rh * 2 + 1] + s_bias[co + 1], 0.f);
                        __half h0, l0, h1, l1;
                        split_fp16(y0, h0, l0);
                        split_fp16(y1, h1, l1);
                        dH[co >> 1] = (uint32_t)__half_as_ushort(h0) | ((uint32_t)__half_as_ushort(h1) << 16);
                        dL[co >> 1] = (uint32_t)__half_as_ushort(l0) | ((uint32_t)__half_as_ushort(l1) << 16);
                    }
                }
            } else {
                bool valid = false;
                if ((r - rbase) < HALF_ROWS && r < PROWS) {
                    const int rd = r / PW, rm = r - rd * PW;
                    valid = (rd >= 1 && rd <= HH && rm >= 1 && rm <= WW);
                }
                if (valid) {
                    #pragma unroll
                    for (int nt = 0; nt < 6; ++nt) {
                        const int co = nt * 8 + (lane & 3) * 2;
                        pool[nt][0] += fmaxf(C[i][nt][rh * 2]     + s_bias[co],     0.f);
                        pool[nt][1] += fmaxf(C[i][nt][rh * 2 + 1] + s_bias[co + 1], 0.f);
                    }
                }
            }
        }
    }

    if (PHASE == 1) {
        #pragma unroll
        for (int nt = 0; nt < 6; ++nt) {
            #pragma unroll
            for (int e = 0; e < 2; ++e) {
                float v = pool[nt][e];
                v += __shfl_xor_sync(0xffffffffu, v, 4);
                v += __shfl_xor_sync(0xffffffffu, v, 8);
                v += __shfl_xor_sync(0xffffffffu, v, 16);
                if ((lane >> 2) == 0)
                    s_pool[wid * FF + nt * 8 + lane * 2 + e] = v;
            }
        }
        __syncthreads();
        if (tid < FF) {
            float s = 0.f;
            #pragma unroll
            for (int ww = 0; ww < 8; ++ww) s += s_pool[ww * FF + tid];
            g_feats[(frame * 2 + half) * FF + tid] = s;
        }
    }
}

// ---------------------------------------------------------------------------
// Kernel 4: LSTM + BN2 + head. One warp per batch element. x-dots for ALL t
// precomputed in parallel; only the 8-term h-recurrence is sequential.
// ---------------------------------------------------------------------------
__device__ __forceinline__ float fsig(float x)  { return __fdividef(1.f, 1.f + __expf(-x)); }
__device__ __forceinline__ float ftanh(float x) { return 1.f - __fdividef(2.f, __expf(2.f * x) + 1.f); }

__global__ void __launch_bounds__(32, 1)
lstm_kernel(const float* __restrict__ wf,  const float* __restrict__ bf,
            const float* __restrict__ wi1, const float* __restrict__ bi1,
            const float* __restrict__ wi2, const float* __restrict__ bi2,
            const float* __restrict__ wo,  const float* __restrict__ bo,
            const float* __restrict__ bn1_g, const float* __restrict__ bn1_b,
            const float* __restrict__ bn1_m, const float* __restrict__ bn1_v,
            const float* __restrict__ bn2_g, const float* __restrict__ bn2_b,
            const float* __restrict__ bn2_m, const float* __restrict__ bn2_v,
            const float* __restrict__ w_out, const float* __restrict__ b_out,
            float* __restrict__ out)
{
    __shared__ float s_x[TT][FF];
    __shared__ float s_g[TT][32];
    __shared__ float s_sc1[FF], s_sh1[FF];

    const int b    = blockIdx.x;
    const int lane = threadIdx.x;
    const int u    = lane & 7;

    const float* Wg = (lane < 8) ? wf : (lane < 16) ? wi1 : (lane < 24) ? wi2 : wo;
    const float* Bg = (lane < 8) ? bf : (lane < 16) ? bi1 : (lane < 24) ? bi2 : bo;
    float wcol[FF + UU];
    #pragma unroll
    for (int k = 0; k < FF + UU; ++k) wcol[k] = Wg[k * UU + u];
    const float bgate = Bg[u];

    for (int co = lane; co < FF; co += 32) {
        const float sc = bn1_g[co] * rsqrtf(bn1_v[co] + EPSB);
        s_sc1[co] = sc * (1.f / (float)FRAME_PIX);
        s_sh1[co] = bn1_b[co] - bn1_m[co] * sc;
    }
    __syncwarp();

    for (int i = lane; i < TT * FF; i += 32) {
        const int t = i / FF, co = i - t * FF;
        const int fr = (b << 5) + t;
        const float ps = g_feats[(fr * 2) * FF + co] + g_feats[(fr * 2 + 1) * FF + co];
        s_x[t][co] = ps * s_sc1[co] + s_sh1[co];
    }
    __syncwarp();

    // parallel x-dot precompute (each lane = its gate column, all t)
    #pragma unroll 4
    for (int t = 0; t < TT; ++t) {
        float a0 = 0.f, a1 = 0.f, a2 = 0.f, a3 = 0.f;
        #pragma unroll
        for (int k = 0; k < FF; k += 4) {
            a0 += s_x[t][k]     * wcol[k];
            a1 += s_x[t][k + 1] * wcol[k + 1];
            a2 += s_x[t][k + 2] * wcol[k + 2];
            a3 += s_x[t][k + 3] * wcol[k + 3];
        }
        s_g[t][lane] = bgate + ((a0 + a1) + (a2 + a3));
    }
    __syncwarp();

    const float sc2  = bn2_g[u] * rsqrtf(bn2_v[u] + EPSB);
    const float coef = sc2 * w_out[u];
    float outc = b_out[0];
    #pragma unroll
    for (int j = 0; j < UU; ++j) {
        const float s2 = bn2_g[j] * rsqrtf(bn2_v[j] + EPSB);
        outc += (bn2_b[j] - bn2_m[j] * s2) * w_out[j];
    }

    float c = 0.f, h = 0.f;
    for (int t = 0; t < TT; ++t) {
        float a = s_g[t][lane];
        #pragma unroll
        for (int j = 0; j < UU; ++j)
            a += __shfl_sync(0xffffffffu, h, j) * wcol[FF + j];

        const float fg = fsig (__shfl_sync(0xffffffffu, a, u));
        const float ig = fsig (__shfl_sync(0xffffffffu, a, u + 8));
        const float gg = ftanh(__shfl_sync(0xffffffffu, a, u + 16));
        const float og = fsig (__shfl_sync(0xffffffffu, a, u + 24));
        c = fg * c + ig * gg;
        h = og * ftanh(c);

        float p = h * coef;
        p += __shfl_xor_sync(0xffffffffu, p, 1);
        p += __shfl_xor_sync(0xffffffffu, p, 2);
        p += __shfl_xor_sync(0xffffffffu, p, 4);
        if (lane == 0) out[(b << 5) + t] = p + outc;
    }
}

// ---------------------------------------------------------------------------
// Launch
// ---------------------------------------------------------------------------
extern "C" void kernel_launch(void* const* d_in, const int* in_sizes, int n_in,
                              void* d_out, int out_size)
{
    const float* x     = (const float*)d_in[0];
    const float* w1    = (const float*)d_in[1];
    const float* b1    = (const float*)d_in[2];
    const float* w2    = (const float*)d_in[3];
    const float* b2    = (const float*)d_in[4];
    const float* w3    = (const float*)d_in[5];
    const float* b3    = (const float*)d_in[6];
    const float* bn1_g = (const float*)d_in[7];
    const float* bn1_b = (const float*)d_in[8];
    const float* bn1_m = (const float*)d_in[9];
    const float* bn1_v = (const float*)d_in[10];
    const float* wf    = (const float*)d_in[11];
    const float* bf    = (const float*)d_in[12];
    const float* wi1   = (const float*)d_in[13];
    const float* bi1   = (const float*)d_in[14];
    const float* wi2   = (const float*)d_in[15];
    const float* bi2   = (const float*)d_in[16];
    const float* wo    = (const float*)d_in[17];
    const float* bo    = (const float*)d_in[18];
    const float* bn2_g = (const float*)d_in[19];
    const float* bn2_b = (const float*)d_in[20];
    const float* bn2_m = (const float*)d_in[21];
    const float* bn2_v = (const float*)d_in[22];
    const float* w_out = (const float*)d_in[23];
    const float* b_out = (const float*)d_in[24];
    float* out = (float*)d_out;

    cudaFuncSetAttribute(convmm_kernel<0>, cudaFuncAttributeMaxDynamicSharedMemorySize, CONV_SMEM);
    cudaFuncSetAttribute(convmm_kernel<1>, cudaFuncAttributeMaxDynamicSharedMemorySize, CONV_SMEM);

    __half *a1h = nullptr, *a1l = nullptr, *a2h = nullptr, *a2l = nullptr;
    uint32_t* bfrag = nullptr;
    cudaGetSymbolAddress((void**)&a1h, g_a1h);
    cudaGetSymbolAddress((void**)&a1l, g_a1l);
    cudaGetSymbolAddress((void**)&a2h, g_a2h);
    cudaGetSymbolAddress((void**)&a2l, g_a2l);
    cudaGetSymbolAddress((void**)&bfrag, g_bfrag);

    prep_kernel<<<2, 256>>>(w2, w3);
    conv1_kernel<<<NFRAMES, 256>>>(x, w1, b1);
    convmm_kernel<0><<<NFRAMES * 2, 256, CONV_SMEM>>>(a1h, a1l, bfrag, b2);
    convmm_kernel<1><<<NFRAMES * 2, 256, CONV_SMEM>>>(a2h, a2l, bfrag + 27 * 6 * 64, b3);
    lstm_kernel<<<BB, 32>>>(wf, bf, wi1, bi1, wi2, bi2, wo, bo,
                            bn1_g, bn1_b, bn1_m, bn1_v,
                            bn2_g, bn2_b, bn2_m, bn2_v,
                            w_out, b_out, out);
}

// round 8
// speedup vs baseline: 4.8780x; 1.4780x over previous
#include <cuda_runtime.h>
#include <cuda_fp16.h>
#include <cstdint>
#include <math.h>

// Problem constants
#define BB   32
#define TT   32
#define HH   28
#define WW   28
#define FF   48
#define UU   8
#define EPSB 1e-3f
#define NFRAMES (BB*TT)            // 1024
#define FRAME_PIX (HH*WW)          // 784
#define PW   30                    // padded width
#define PROWS (PW*PW)              // 900 padded pixel-rows per frame

// ---------------------------------------------------------------------------
// Warp-MMA helpers
// ---------------------------------------------------------------------------
__device__ __forceinline__ uint32_t smem_u32(const void* p) {
    return (uint32_t)__cvta_generic_to_shared(p);
}
__device__ __forceinline__ void ldmx4(uint32_t a[4], uint32_t addr) {
    asm volatile("ldmatrix.sync.aligned.m8n8.x4.shared.b16 {%0,%1,%2,%3}, [%4];"
                 : "=r"(a[0]), "=r"(a[1]), "=r"(a[2]), "=r"(a[3]) : "r"(addr));
}
__device__ __forceinline__ void mma_fp16(float c[4], const uint32_t a[4],
                                         uint32_t b0, uint32_t b1) {
    asm volatile("mma.sync.aligned.m16n8k16.row.col.f32.f16.f16.f32 "
                 "{%0,%1,%2,%3},{%4,%5,%6,%7},{%8,%9},{%0,%1,%2,%3};"
                 : "+f"(c[0]), "+f"(c[1]), "+f"(c[2]), "+f"(c[3])
                 : "r"(a[0]), "r"(a[1]), "r"(a[2]), "r"(a[3]), "r"(b0), "r"(b1));
}
__device__ __forceinline__ void cpa16(uint32_t dst, const void* src, uint32_t srcbytes) {
    asm volatile("cp.async.cg.shared.global [%0], [%1], 16, %2;"
                 :: "r"(dst), "l"(src), "r"(srcbytes));
}
__device__ __forceinline__ void cpa_wait_all() {
    asm volatile("cp.async.commit_group;\n\tcp.async.wait_group 0;" ::: "memory");
}

// ---------------------------------------------------------------------------
// Scratch: single-rounded fp16 activations [frame][900 padded rows][48]
// ---------------------------------------------------------------------------
__device__ __align__(16) __half g_a1[NFRAMES * PROWS * FF];
__device__ __align__(16) __half g_a2[NFRAMES * PROWS * FF];
__device__ __align__(16) uint32_t g_bfrag[2][27 * 6 * 64];  // fp16x2 fragments
__device__ float g_feats[NFRAMES * 2 * FF];

// ---------------------------------------------------------------------------
// Kernel 0: pre-fragment conv weights (identical for all CTAs; built once/run)
// group = (tap*3+kc)*6+nt, slot = lane*2+reg
// ---------------------------------------------------------------------------
__global__ void prep_kernel(const float* __restrict__ w2,
                            const float* __restrict__ w3)
{
    const float* w = (blockIdx.x == 0) ? w2 : w3;
    uint32_t* dst = g_bfrag[blockIdx.x];
    for (int i = threadIdx.x; i < 162 * 64; i += 256) {
        const int group = i >> 6;
        const int slot  = i & 63;
        const int l     = slot >> 1;
        const int reg   = slot & 1;
        const int tapkc = group / 6;
        const int nt    = group - tapkc * 6;
        const int tap   = tapkc / 3;
        const int kc    = tapkc - tap * 3;
        const int n     = nt * 8 + (l >> 2);               // co
        const int k     = kc * 16 + (l & 3) * 2 + reg * 8; // ci
        const __half h0 = __float2half_rn(w[(tap * FF + k)     * FF + n]);
        const __half h1 = __float2half_rn(w[(tap * FF + k + 1) * FF + n]);
        dst[i] = (uint32_t)__half_as_ushort(h0) | ((uint32_t)__half_as_ushort(h1) << 16);
    }
}

// ---------------------------------------------------------------------------
// Kernel 1: conv1 (C=1 -> 48) + ReLU, direct fp32; writes fp16.
// ---------------------------------------------------------------------------
__global__ void conv1_kernel(const float* __restrict__ x,
                             const float* __restrict__ w1,
                             const float* __restrict__ b1)
{
    __shared__ float s_f[FRAME_PIX];
    __shared__ float s_w[9 * FF];
    __shared__ float s_b[FF];

    const int frame = blockIdx.x;
    const int tid   = threadIdx.x;

    for (int i = tid; i < FRAME_PIX; i += 256) s_f[i] = x[frame * FRAME_PIX + i];
    for (int i = tid; i < 9 * FF;   i += 256) s_w[i] = w1[i];
    if (tid < FF) s_b[tid] = b1[tid];
    __syncthreads();

    const size_t fbase = (size_t)frame * PROWS * FF;
    for (int idx = tid; idx < FRAME_PIX * FF; idx += 256) {
        const int co = idx % FF;
        const int p  = idx / FF;
        const int h  = p / WW;
        const int w  = p % WW;
        float acc = s_b[co];
        #pragma unroll
        for (int dy = 0; dy < 3; ++dy) {
            const int hh = h + dy - 1;
            if ((unsigned)hh < (unsigned)HH) {
                #pragma unroll
                for (int dx = 0; dx < 3; ++dx) {
                    const int wx = w + dx - 1;
                    if ((unsigned)wx < (unsigned)WW)
                        acc += s_f[hh * WW + wx] * s_w[(dy * 3 + dx) * FF + co];
                }
            }
        }
        const int r = (h + 1) * PW + (w + 1);
        g_a1[fbase + (size_t)r * FF + co] = __float2half_rn(fmaxf(acc, 0.f));
    }
}

// ---------------------------------------------------------------------------
// Kernel 2/3: 48->48 conv via mma.sync, SINGLE-pass fp16.
// CTA = (frame, half). A slab 544 rows x 112B (conflict-free ldmatrix),
// cp.async zero-fill halo. Prebuilt B frags cp.async'd, register-hoisted.
// Warp = 4 M-tiles; 6 MMAs per (tapkc, tile).
// PHASE 0: writes act2. PHASE 1: pools ReLU outputs per (frame,half).
// ---------------------------------------------------------------------------
#define SLAB_ROWS 544
#define A_STRIDE  112                          // 48 fp16 data + 8 pad
#define A_BYTES   (SLAB_ROWS * A_STRIDE)       // 60928
#define B_BYTES   (27 * 6 * 64 * 4)            // 41472
#define OFF_A     0
#define OFF_B     (OFF_A + A_BYTES)            // 60928
#define OFF_BI    (OFF_B + B_BYTES)            // 102400
#define CONV_SMEM (OFF_BI + FF * 4)            // 102592
#define MT_TILES  29
#define HALF_ROWS 450
#define T_PER_W   4

template <int PHASE>
__global__ void __launch_bounds__(256, 1)
convmm_kernel(const __half* __restrict__ in,
              const uint32_t* __restrict__ bfrag,
              const float* __restrict__ bias)
{
    extern __shared__ __align__(16) char smem[];
    __shared__ float s_pool[8 * FF];

    const int frame = blockIdx.x >> 1;
    const int half  = blockIdx.x & 1;
    const int rbase = half * HALF_ROWS;
    const int tid   = threadIdx.x;
    const int wid   = tid >> 5;
    const int lane  = tid & 31;
    const uint32_t smb = smem_u32(smem);

    float* s_bias = (float*)(smem + OFF_BI);
    if (tid < FF) s_bias[tid] = bias[tid];

    // ---- B fragments: straight 16B async copies from prebuilt global ----
    for (int i = tid; i < B_BYTES / 16; i += 256)
        cpa16(smb + OFF_B + i * 16, (const char*)bfrag + i * 16, 16);

    // ---- A slab via cp.async, zero-fill for halo/padding ----
    {
        const char* src = (const char*)(in + (size_t)frame * PROWS * FF);
        for (int i = tid; i < SLAB_ROWS * 7; i += 256) {
            const int s   = i / 7;
            const int blk = i - s * 7;
            const int r   = rbase - 31 + s;
            bool valid = false;
            if (r >= 0 && r < PROWS && blk < 6) {
                const int rd = r / PW, rm = r - rd * PW;
                valid = (rd >= 1 && rd <= HH && rm >= 1 && rm <= WW);
            }
            const long off = valid ? ((long)r * 96 + blk * 16) : 0;
            const uint32_t n = valid ? 16u : 0u;
            cpa16(smb + OFF_A + s * A_STRIDE + blk * 16, src + off, n);
        }
    }
    cpa_wait_all();
    __syncthreads();

    const uint32_t laneoff = (uint32_t)((lane & 15) * A_STRIDE + ((lane >> 4) << 4));
    const uint32_t* s_b = (const uint32_t*)(smem + OFF_B);

    // Per-warp tiles (clamped; duplicates discarded at epilogue)
    int mtv[T_PER_W];
    uint32_t abase[T_PER_W];
    #pragma unroll
    for (int i = 0; i < T_PER_W; ++i) {
        int mt = wid + 8 * i;
        mtv[i] = mt;
        if (mt > 28) mt = 28;
        abase[i] = smb + OFF_A + (uint32_t)((31 + mt * 16) * A_STRIDE) + laneoff;
    }

    float C[T_PER_W][6][4];
    #pragma unroll
    for (int i = 0; i < T_PER_W; ++i)
        #pragma unroll
        for (int nt = 0; nt < 6; ++nt) {
            C[i][nt][0] = 0.f; C[i][nt][1] = 0.f; C[i][nt][2] = 0.f; C[i][nt][3] = 0.f;
        }

    #pragma unroll 1
    for (int tap = 0; tap < 9; ++tap) {
        const int dy = tap / 3;
        const int aoff = ((dy - 1) * PW + (tap - dy * 3) - 1) * A_STRIDE;
        #pragma unroll
        for (int kc = 0; kc < 3; ++kc) {
            uint2 BW[6];
            const int bbase = ((tap * 3 + kc) * 6) * 64 + lane * 2;
            #pragma unroll
            for (int nt = 0; nt < 6; ++nt)
                BW[nt] = *(const uint2*)(s_b + bbase + nt * 64);
            #pragma unroll
            for (int i = 0; i < T_PER_W; ++i) {
                uint32_t a[4];
                ldmx4(a, abase[i] + (uint32_t)(aoff + kc * 32));
                #pragma unroll
                for (int nt = 0; nt < 6; ++nt)
                    mma_fp16(C[i][nt], a, BW[nt].x, BW[nt].y);
            }
        }
    }

    // ---- Epilogue ----
    float pool[6][2];
    if (PHASE == 1) {
        #pragma unroll
        for (int nt = 0; nt < 6; ++nt) { pool[nt][0] = 0.f; pool[nt][1] = 0.f; }
    }

    #pragma unroll
    for (int i = 0; i < T_PER_W; ++i) {
        if (mtv[i] > 28) continue;     // clamped duplicate tile
        #pragma unroll
        for (int rh = 0; rh < 2; ++rh) {
            const int r = rbase + mtv[i] * 16 + (lane >> 2) + rh * 8;
            if (PHASE == 0) {
                if (r < PROWS) {
                    uint32_t* d = (uint32_t*)(g_a2 + ((size_t)frame * PROWS + r) * FF);
                    #pragma unroll
                    for (int nt = 0; nt < 6; ++nt) {
                        const int co = nt * 8 + (lane & 3) * 2;
                        const __half h0 = __float2half_rn(fmaxf(C[i][nt][rh * 2]     + s_bias[co],     0.f));
                        const __half h1 = __float2half_rn(fmaxf(C[i][nt][rh * 2 + 1] + s_bias[co + 1], 0.f));
                        d[co >> 1] = (uint32_t)__half_as_ushort(h0) | ((uint32_t)__half_as_ushort(h1) << 16);
                    }
                }
            } else {
                bool valid = false;
                if ((r - rbase) < HALF_ROWS && r < PROWS) {
                    const int rd = r / PW, rm = r - rd * PW;
                    valid = (rd >= 1 && rd <= HH && rm >= 1 && rm <= WW);
                }
                if (valid) {
                    #pragma unroll
                    for (int nt = 0; nt < 6; ++nt) {
                        const int co = nt * 8 + (lane & 3) * 2;
                        pool[nt][0] += fmaxf(C[i][nt][rh * 2]     + s_bias[co],     0.f);
                        pool[nt][1] += fmaxf(C[i][nt][rh * 2 + 1] + s_bias[co + 1], 0.f);
                    }
                }
            }
        }
    }

    if (PHASE == 1) {
        #pragma unroll
        for (int nt = 0; nt < 6; ++nt) {
            #pragma unroll
            for (int e = 0; e < 2; ++e) {
                float v = pool[nt][e];
                v += __shfl_xor_sync(0xffffffffu, v, 4);
                v += __shfl_xor_sync(0xffffffffu, v, 8);
                v += __shfl_xor_sync(0xffffffffu, v, 16);
                if ((lane >> 2) == 0)
                    s_pool[wid * FF + nt * 8 + lane * 2 + e] = v;
            }
        }
        __syncthreads();
        if (tid < FF) {
            float s = 0.f;
            #pragma unroll
            for (int ww = 0; ww < 8; ++ww) s += s_pool[ww * FF + tid];
            g_feats[(frame * 2 + half) * FF + tid] = s;
        }
    }
}

// ---------------------------------------------------------------------------
// Kernel 4: LSTM + BN2 + head. One warp per batch element. x-dots for ALL t
// precomputed in parallel; only the 8-term h-recurrence is sequential.
// ---------------------------------------------------------------------------
__device__ __forceinline__ float fsig(float x)  { return __fdividef(1.f, 1.f + __expf(-x)); }
__device__ __forceinline__ float ftanh(float x) { return 1.f - __fdividef(2.f, __expf(2.f * x) + 1.f); }

__global__ void __launch_bounds__(32, 1)
lstm_kernel(const float* __restrict__ wf,  const float* __restrict__ bf,
            const float* __restrict__ wi1, const float* __restrict__ bi1,
            const float* __restrict__ wi2, const float* __restrict__ bi2,
            const float* __restrict__ wo,  const float* __restrict__ bo,
            const float* __restrict__ bn1_g, const float* __restrict__ bn1_b,
            const float* __restrict__ bn1_m, const float* __restrict__ bn1_v,
            const float* __restrict__ bn2_g, const float* __restrict__ bn2_b,
            const float* __restrict__ bn2_m, const float* __restrict__ bn2_v,
            const float* __restrict__ w_out, const float* __restrict__ b_out,
            float* __restrict__ out)
{
    __shared__ float s_x[TT][FF];
    __shared__ float s_g[TT][32];
    __shared__ float s_sc1[FF], s_sh1[FF];

    const int b    = blockIdx.x;
    const int lane = threadIdx.x;
    const int u    = lane & 7;

    const float* Wg = (lane < 8) ? wf : (lane < 16) ? wi1 : (lane < 24) ? wi2 : wo;
    const float* Bg = (lane < 8) ? bf : (lane < 16) ? bi1 : (lane < 24) ? bi2 : bo;
    float wcol[FF + UU];
    #pragma unroll
    for (int k = 0; k < FF + UU; ++k) wcol[k] = Wg[k * UU + u];
    const float bgate = Bg[u];

    for (int co = lane; co < FF; co += 32) {
        const float sc = bn1_g[co] * rsqrtf(bn1_v[co] + EPSB);
        s_sc1[co] = sc * (1.f / (float)FRAME_PIX);
        s_sh1[co] = bn1_b[co] - bn1_m[co] * sc;
    }
    __syncwarp();

    for (int i = lane; i < TT * FF; i += 32) {
        const int t = i / FF, co = i - t * FF;
        const int fr = (b << 5) + t;
        const float ps = g_feats[(fr * 2) * FF + co] + g_feats[(fr * 2 + 1) * FF + co];
        s_x[t][co] = ps * s_sc1[co] + s_sh1[co];
    }
    __syncwarp();

    // parallel x-dot precompute (each lane = its gate column, all t)
    #pragma unroll 4
    for (int t = 0; t < TT; ++t) {
        float a0 = 0.f, a1 = 0.f, a2 = 0.f, a3 = 0.f;
        #pragma unroll
        for (int k = 0; k < FF; k += 4) {
            a0 += s_x[t][k]     * wcol[k];
            a1 += s_x[t][k + 1] * wcol[k + 1];
            a2 += s_x[t][k + 2] * wcol[k + 2];
            a3 += s_x[t][k + 3] * wcol[k + 3];
        }
        s_g[t][lane] = bgate + ((a0 + a1) + (a2 + a3));
    }
    __syncwarp();

    const float sc2  = bn2_g[u] * rsqrtf(bn2_v[u] + EPSB);
    const float coef = sc2 * w_out[u];
    float outc = b_out[0];
    #pragma unroll
    for (int j = 0; j < UU; ++j) {
        const float s2 = bn2_g[j] * rsqrtf(bn2_v[j] + EPSB);
        outc += (bn2_b[j] - bn2_m[j] * s2) * w_out[j];
    }

    float c = 0.f, h = 0.f;
    for (int t = 0; t < TT; ++t) {
        float a = s_g[t][lane];
        #pragma unroll
        for (int j = 0; j < UU; ++j)
            a += __shfl_sync(0xffffffffu, h, j) * wcol[FF + j];

        const float fg = fsig (__shfl_sync(0xffffffffu, a, u));
        const float ig = fsig (__shfl_sync(0xffffffffu, a, u + 8));
        const float gg = ftanh(__shfl_sync(0xffffffffu, a, u + 16));
        const float og = fsig (__shfl_sync(0xffffffffu, a, u + 24));
        c = fg * c + ig * gg;
        h = og * ftanh(c);

        float p = h * coef;
        p += __shfl_xor_sync(0xffffffffu, p, 1);
        p += __shfl_xor_sync(0xffffffffu, p, 2);
        p += __shfl_xor_sync(0xffffffffu, p, 4);
        if (lane == 0) out[(b << 5) + t] = p + outc;
    }
}

// ---------------------------------------------------------------------------
// Launch
// ---------------------------------------------------------------------------
extern "C" void kernel_launch(void* const* d_in, const int* in_sizes, int n_in,
                              void* d_out, int out_size)
{
    const float* x     = (const float*)d_in[0];
    const float* w1    = (const float*)d_in[1];
    const float* b1    = (const float*)d_in[2];
    const float* w2    = (const float*)d_in[3];
    const float* b2    = (const float*)d_in[4];
    const float* w3    = (const float*)d_in[5];
    const float* b3    = (const float*)d_in[6];
    const float* bn1_g = (const float*)d_in[7];
    const float* bn1_b = (const float*)d_in[8];
    const float* bn1_m = (const float*)d_in[9];
    const float* bn1_v = (const float*)d_in[10];
    const float* wf    = (const float*)d_in[11];
    const float* bf    = (const float*)d_in[12];
    const float* wi1   = (const float*)d_in[13];
    const float* bi1   = (const float*)d_in[14];
    const float* wi2   = (const float*)d_in[15];
    const float* bi2   = (const float*)d_in[16];
    const float* wo    = (const float*)d_in[17];
    const float* bo    = (const float*)d_in[18];
    const float* bn2_g = (const float*)d_in[19];
    const float* bn2_b = (const float*)d_in[20];
    const float* bn2_m = (const float*)d_in[21];
    const float* bn2_v = (const float*)d_in[22];
    const float* w_out = (const float*)d_in[23];
    const float* b_out = (const float*)d_in[24];
    float* out = (float*)d_out;

    cudaFuncSetAttribute(convmm_kernel<0>, cudaFuncAttributeMaxDynamicSharedMemorySize, CONV_SMEM);
    cudaFuncSetAttribute(convmm_kernel<1>, cudaFuncAttributeMaxDynamicSharedMemorySize, CONV_SMEM);

    __half *a1 = nullptr, *a2 = nullptr;
    uint32_t* bfrag = nullptr;
    cudaGetSymbolAddress((void**)&a1, g_a1);
    cudaGetSymbolAddress((void**)&a2, g_a2);
    cudaGetSymbolAddress((void**)&bfrag, g_bfrag);

    prep_kernel<<<2, 256>>>(w2, w3);
    conv1_kernel<<<NFRAMES, 256>>>(x, w1, b1);
    convmm_kernel<0><<<NFRAMES * 2, 256, CONV_SMEM>>>(a1, bfrag, b2);
    convmm_kernel<1><<<NFRAMES * 2, 256, CONV_SMEM>>>(a2, bfrag + 27 * 6 * 64, b3);
    lstm_kernel<<<BB, 32>>>(wf, bf, wi1, bi1, wi2, bi2, wo, bo,
                            bn1_g, bn1_b, bn1_m, bn1_v,
                            bn2_g, bn2_b, bn2_m, bn2_v,
                            w_out, b_out, out);
}

// round 10
// speedup vs baseline: 6.1807x; 1.2671x over previous
#include <cuda_runtime.h>
#include <cuda_fp16.h>
#include <cstdint>
#include <math.h>

// Problem constants
#define BB   32
#define TT   32
#define HH   28
#define WW   28
#define FF   48
#define UU   8
#define EPSB 1e-3f
#define NFRAMES (BB*TT)            // 1024
#define FRAME_PIX (HH*WW)          // 784
#define PW   30                    // padded width
#define PROWS (PW*PW)              // 900 padded pixel-rows per frame

// ---------------------------------------------------------------------------
// Warp-MMA helpers
// ---------------------------------------------------------------------------
__device__ __forceinline__ uint32_t smem_u32(const void* p) {
    return (uint32_t)__cvta_generic_to_shared(p);
}
__device__ __forceinline__ void ldmx4(uint32_t a[4], uint32_t addr) {
    asm volatile("ldmatrix.sync.aligned.m8n8.x4.shared.b16 {%0,%1,%2,%3}, [%4];"
                 : "=r"(a[0]), "=r"(a[1]), "=r"(a[2]), "=r"(a[3]) : "r"(addr));
}
__device__ __forceinline__ void mma_fp16(float c[4], const uint32_t a[4],
                                         uint32_t b0, uint32_t b1) {
    asm volatile("mma.sync.aligned.m16n8k16.row.col.f32.f16.f16.f32 "
                 "{%0,%1,%2,%3},{%4,%5,%6,%7},{%8,%9},{%0,%1,%2,%3};"
                 : "+f"(c[0]), "+f"(c[1]), "+f"(c[2]), "+f"(c[3])
                 : "r"(a[0]), "r"(a[1]), "r"(a[2]), "r"(a[3]), "r"(b0), "r"(b1));
}
__device__ __forceinline__ void cpa16(uint32_t dst, const void* src, uint32_t srcbytes) {
    asm volatile("cp.async.cg.shared.global [%0], [%1], 16, %2;"
                 :: "r"(dst), "l"(src), "r"(srcbytes));
}
#define CPA_COMMIT() asm volatile("cp.async.commit_group;" ::: "memory")
#define CPA_WAIT(n)  asm volatile("cp.async.wait_group %0;" :: "n"(n) : "memory")

// ---------------------------------------------------------------------------
// Scratch
// ---------------------------------------------------------------------------
__device__ __align__(16) __half g_a1[NFRAMES * PROWS * FF];
__device__ __align__(16) __half g_a2[NFRAMES * PROWS * FF];
__device__ __align__(16) uint32_t g_bfrag[2][27 * 6 * 64];  // fp16x2 fragments
__device__ float g_feats[NFRAMES * 2 * FF];

// ---------------------------------------------------------------------------
// Kernel 0: pre-fragment conv weights (once per run)
// ---------------------------------------------------------------------------
__global__ void prep_kernel(const float* __restrict__ w2,
                            const float* __restrict__ w3)
{
    const float* w = (blockIdx.x == 0) ? w2 : w3;
    uint32_t* dst = g_bfrag[blockIdx.x];
    for (int i = threadIdx.x; i < 162 * 64; i += 256) {
        const int group = i >> 6;
        const int slot  = i & 63;
        const int l     = slot >> 1;
        const int reg   = slot & 1;
        const int tapkc = group / 6;
        const int nt    = group - tapkc * 6;
        const int tap   = tapkc / 3;
        const int kc    = tapkc - tap * 3;
        const int n     = nt * 8 + (l >> 2);
        const int k     = kc * 16 + (l & 3) * 2 + reg * 8;
        const __half h0 = __float2half_rn(w[(tap * FF + k)     * FF + n]);
        const __half h1 = __float2half_rn(w[(tap * FF + k + 1) * FF + n]);
        dst[i] = (uint32_t)__half_as_ushort(h0) | ((uint32_t)__half_as_ushort(h1) << 16);
    }
}

// ---------------------------------------------------------------------------
// Kernel 1: conv1 (C=1 -> 48) + ReLU. Zero-padded smem image (no tap
// branches), thread = (pixel, co-pair), float2 weights, half2 4B stores.
// ---------------------------------------------------------------------------
__global__ void __launch_bounds__(256, 1)
conv1_kernel(const float* __restrict__ x,
             const float* __restrict__ w1,
             const float* __restrict__ b1)
{
    __shared__ float  s_f[PROWS];          // 30x30, zero halo
    __shared__ float2 s_w[9 * 24];
    __shared__ float2 s_b2[24];

    const int frame = blockIdx.x;
    const int tid   = threadIdx.x;

    for (int i = tid; i < PROWS; i += 256) {
        const int r = i / PW, c = i - r * PW;
        float v = 0.f;
        if (r >= 1 && r <= HH && c >= 1 && c <= WW)
            v = x[frame * FRAME_PIX + (r - 1) * WW + (c - 1)];
        s_f[i] = v;
    }
    for (int i = tid; i < 9 * 24; i += 256) s_w[i] = ((const float2*)w1)[i];
    if (tid < 24) s_b2[tid] = ((const float2*)b1)[tid];
    __syncthreads();

    uint32_t* outp = (uint32_t*)(g_a1 + (size_t)frame * PROWS * FF);
    for (int idx = tid; idx < FRAME_PIX * 24; idx += 256) {
        const int p   = idx / 24;
        const int co2 = idx - p * 24;
        const int h   = p / WW;
        const int w   = p - h * WW;
        const int base = h * PW + w;        // padded top-left tap
        float2 acc = s_b2[co2];
        #pragma unroll
        for (int dy = 0; dy < 3; ++dy) {
            #pragma unroll
            for (int dx = 0; dx < 3; ++dx) {
                const float v = s_f[base + dy * PW + dx];
                const float2 fw = s_w[(dy * 3 + dx) * 24 + co2];
                acc.x += v * fw.x;
                acc.y += v * fw.y;
            }
        }
        const __half2 hv = __floats2half2_rn(fmaxf(acc.x, 0.f), fmaxf(acc.y, 0.f));
        outp[((h + 1) * PW + (w + 1)) * 24 + co2] = *(const uint32_t*)&hv;
    }
}

// ---------------------------------------------------------------------------
// Kernel 2/3: persistent double-buffered conv48 via mma.sync (fp16, 1 pass).
// grid = 148 (1 CTA/SM). Each CTA walks items (frame,half) strided by 148;
// B frags + bias loaded ONCE; A slab for item k+1 cp.async'd while item k
// computes (wait_group 1 pattern).
// ---------------------------------------------------------------------------
#define SLAB_ROWS 544
#define A_STRIDE  112
#define A_BYTES   (SLAB_ROWS * A_STRIDE)       // 60928
#define B_BYTES   (27 * 6 * 64 * 4)            // 41472
#define OFF_A0    0
#define OFF_A1    (OFF_A0 + A_BYTES)           // 60928
#define OFF_B     (OFF_A1 + A_BYTES)           // 121856
#define OFF_BI    (OFF_B + B_BYTES)            // 163328
#define CONV_SMEM (OFF_BI + FF * 4)            // 163520
#define HALF_ROWS 450
#define T_PER_W   4
#define GRID_CONV 148
#define N_ITEMS   (NFRAMES * 2)                // 2048

__device__ __forceinline__ void issue_slab(uint32_t dst, const __half* __restrict__ in,
                                           int item, int tid)
{
    const int frame = item >> 1;
    const int rbase = (item & 1) * HALF_ROWS;
    const char* src = (const char*)(in + (size_t)frame * PROWS * FF);
    for (int i = tid; i < SLAB_ROWS * 7; i += 256) {
        const int s   = i / 7;
        const int blk = i - s * 7;
        const int r   = rbase - 31 + s;
        bool valid = false;
        if (r >= 0 && r < PROWS && blk < 6) {
            const int rd = r / PW, rm = r - rd * PW;
            valid = (rd >= 1 && rd <= HH && rm >= 1 && rm <= WW);
        }
        const long off = valid ? ((long)r * 96 + blk * 16) : 0;
        cpa16(dst + s * A_STRIDE + blk * 16, src + off, valid ? 16u : 0u);
    }
}

template <int PHASE>
__global__ void __launch_bounds__(256, 1)
convmm_kernel(const __half* __restrict__ in,
              const uint32_t* __restrict__ bfrag,
              const float* __restrict__ bias)
{
    extern __shared__ __align__(16) char smem[];
    __shared__ float s_pool[8 * FF];

    const int bid  = blockIdx.x;
    const int tid  = threadIdx.x;
    const int wid  = tid >> 5;
    const int lane = tid & 31;
    const uint32_t smb = smem_u32(smem);
    const int nItems = (N_ITEMS - bid + GRID_CONV - 1) / GRID_CONV;

    float* s_bias = (float*)(smem + OFF_BI);
    if (tid < FF) s_bias[tid] = bias[tid];

    // Group 0: B fragments + first A slab
    for (int i = tid; i < B_BYTES / 16; i += 256)
        cpa16(smb + OFF_B + i * 16, (const char*)bfrag + i * 16, 16);
    issue_slab(smb + OFF_A0, in, bid, tid);
    CPA_COMMIT();

    const uint32_t laneoff = (uint32_t)((lane & 15) * A_STRIDE + ((lane >> 4) << 4));
    const uint32_t* s_b = (const uint32_t*)(smem + OFF_B);

    for (int k = 0; k < nItems; ++k) {
        const int item  = bid + GRID_CONV * k;
        const int frame = item >> 1;
        const int rbase = (item & 1) * HALF_ROWS;
        const uint32_t abuf = smb + ((k & 1) ? OFF_A1 : OFF_A0);

        if (k + 1 < nItems) {
            issue_slab(smb + ((k & 1) ? OFF_A0 : OFF_A1), in, item + GRID_CONV, tid);
            CPA_COMMIT();
            CPA_WAIT(1);
        } else {
            CPA_WAIT(0);
        }
        __syncthreads();

        // Per-warp tiles (clamped; duplicates skipped at epilogue)
        int mtv[T_PER_W];
        uint32_t abase[T_PER_W];
        #pragma unroll
        for (int i = 0; i < T_PER_W; ++i) {
            int mt = wid + 8 * i;
            mtv[i] = mt;
            if (mt > 28) mt = 28;
            abase[i] = abuf + (uint32_t)((31 + mt * 16) * A_STRIDE) + laneoff;
        }

        float C[T_PER_W][6][4];
        #pragma unroll
        for (int i = 0; i < T_PER_W; ++i)
            #pragma unroll
            for (int nt = 0; nt < 6; ++nt) {
                C[i][nt][0] = 0.f; C[i][nt][1] = 0.f; C[i][nt][2] = 0.f; C[i][nt][3] = 0.f;
            }

        #pragma unroll 1
        for (int tap = 0; tap < 9; ++tap) {
            const int dy = tap / 3;
            const int aoff = ((dy - 1) * PW + (tap - dy * 3) - 1) * A_STRIDE;
            #pragma unroll
            for (int kc = 0; kc < 3; ++kc) {
                uint2 BW[6];
                const int bbase = ((tap * 3 + kc) * 6) * 64 + lane * 2;
                #pragma unroll
                for (int nt = 0; nt < 6; ++nt)
                    BW[nt] = *(const uint2*)(s_b + bbase + nt * 64);
                #pragma unroll
                for (int i = 0; i < T_PER_W; ++i) {
                    uint32_t a[4];
                    ldmx4(a, abase[i] + (uint32_t)(aoff + kc * 32));
                    #pragma unroll
                    for (int nt = 0; nt < 6; ++nt)
                        mma_fp16(C[i][nt], a, BW[nt].x, BW[nt].y);
                }
            }
        }

        // ---- Epilogue ----
        float pool[6][2];
        if (PHASE == 1) {
            #pragma unroll
            for (int nt = 0; nt < 6; ++nt) { pool[nt][0] = 0.f; pool[nt][1] = 0.f; }
        }

        #pragma unroll
        for (int i = 0; i < T_PER_W; ++i) {
            if (mtv[i] > 28) continue;
            #pragma unroll
            for (int rh = 0; rh < 2; ++rh) {
                const int r = rbase + mtv[i] * 16 + (lane >> 2) + rh * 8;
                if (PHASE == 0) {
                    if (r < PROWS) {
                        uint32_t* d = (uint32_t*)(g_a2 + ((size_t)frame * PROWS + r) * FF);
                        #pragma unroll
                        for (int nt = 0; nt < 6; ++nt) {
                            const int co = nt * 8 + (lane & 3) * 2;
                            const __half h0 = __float2half_rn(fmaxf(C[i][nt][rh * 2]     + s_bias[co],     0.f));
                            const __half h1 = __float2half_rn(fmaxf(C[i][nt][rh * 2 + 1] + s_bias[co + 1], 0.f));
                            d[co >> 1] = (uint32_t)__half_as_ushort(h0) | ((uint32_t)__half_as_ushort(h1) << 16);
                        }
                    }
                } else {
                    bool valid = false;
                    if ((r - rbase) < HALF_ROWS && r < PROWS) {
                        const int rd = r / PW, rm = r - rd * PW;
                        valid = (rd >= 1 && rd <= HH && rm >= 1 && rm <= WW);
                    }
                    if (valid) {
                        #pragma unroll
                        for (int nt = 0; nt < 6; ++nt) {
                            const int co = nt * 8 + (lane & 3) * 2;
                            pool[nt][0] += fmaxf(C[i][nt][rh * 2]     + s_bias[co],     0.f);
                            pool[nt][1] += fmaxf(C[i][nt][rh * 2 + 1] + s_bias[co + 1], 0.f);
                        }
                    }
                }
            }
        }

        if (PHASE == 1) {
            #pragma unroll
            for (int nt = 0; nt < 6; ++nt) {
                #pragma unroll
                for (int e = 0; e < 2; ++e) {
                    float v = pool[nt][e];
                    v += __shfl_xor_sync(0xffffffffu, v, 4);
                    v += __shfl_xor_sync(0xffffffffu, v, 8);
                    v += __shfl_xor_sync(0xffffffffu, v, 16);
                    if ((lane >> 2) == 0)
                        s_pool[wid * FF + nt * 8 + lane * 2 + e] = v;
                }
            }
            __syncthreads();
            if (tid < FF) {
                float s = 0.f;
                #pragma unroll
                for (int ww = 0; ww < 8; ++ww) s += s_pool[ww * FF + tid];
                g_feats[(frame * 2 + (item & 1)) * FF + tid] = s;
            }
        }
        __syncthreads();   // all reads of abuf done before it is refilled
    }
}

// ---------------------------------------------------------------------------
// Kernel 4: LSTM + BN2 + head. One warp per batch element.
// ---------------------------------------------------------------------------
__device__ __forceinline__ float fsig(float x)  { return __fdividef(1.f, 1.f + __expf(-x)); }
__device__ __forceinline__ float ftanh(float x) { return 1.f - __fdividef(2.f, __expf(2.f * x) + 1.f); }

__global__ void __launch_bounds__(32, 1)
lstm_kernel(const float* __restrict__ wf,  const float* __restrict__ bf,
            const float* __restrict__ wi1, const float* __restrict__ bi1,
            const float* __restrict__ wi2, const float* __restrict__ bi2,
            const float* __restrict__ wo,  const float* __restrict__ bo,
            const float* __restrict__ bn1_g, const float* __restrict__ bn1_b,
            const float* __restrict__ bn1_m, const float* __restrict__ bn1_v,
            const float* __restrict__ bn2_g, const float* __restrict__ bn2_b,
            const float* __restrict__ bn2_m, const float* __restrict__ bn2_v,
            const float* __restrict__ w_out, const float* __restrict__ b_out,
            float* __restrict__ out)
{
    __shared__ float s_x[TT][FF];
    __shared__ float s_g[TT][32];
    __shared__ float s_sc1[FF], s_sh1[FF];

    const int b    = blockIdx.x;
    const int lane = threadIdx.x;
    const int u    = lane & 7;

    const float* Wg = (lane < 8) ? wf : (lane < 16) ? wi1 : (lane < 24) ? wi2 : wo;
    const float* Bg = (lane < 8) ? bf : (lane < 16) ? bi1 : (lane < 24) ? bi2 : bo;
    float wcol[FF + UU];
    #pragma unroll
    for (int k = 0; k < FF + UU; ++k) wcol[k] = Wg[k * UU + u];
    const float bgate = Bg[u];

    for (int co = lane; co < FF; co += 32) {
        const float sc = bn1_g[co] * rsqrtf(bn1_v[co] + EPSB);
        s_sc1[co] = sc * (1.f / (float)FRAME_PIX);
        s_sh1[co] = bn1_b[co] - bn1_m[co] * sc;
    }
    __syncwarp();

    for (int i = lane; i < TT * FF; i += 32) {
        const int t = i / FF, co = i - t * FF;
        const int fr = (b << 5) + t;
        const float ps = g_feats[(fr * 2) * FF + co] + g_feats[(fr * 2 + 1) * FF + co];
        s_x[t][co] = ps * s_sc1[co] + s_sh1[co];
    }
    __syncwarp();

    #pragma unroll 4
    for (int t = 0; t < TT; ++t) {
        float a0 = 0.f, a1 = 0.f, a2 = 0.f, a3 = 0.f;
        #pragma unroll
        for (int k = 0; k < FF; k += 4) {
            a0 += s_x[t][k]     * wcol[k];
            a1 += s_x[t][k + 1] * wcol[k + 1];
            a2 += s_x[t][k + 2] * wcol[k + 2];
            a3 += s_x[t][k + 3] * wcol[k + 3];
        }
        s_g[t][lane] = bgate + ((a0 + a1) + (a2 + a3));
    }
    __syncwarp();

    const float sc2  = bn2_g[u] * rsqrtf(bn2_v[u] + EPSB);
    const float coef = sc2 * w_out[u];
    float outc = b_out[0];
    #pragma unroll
    for (int j = 0; j < UU; ++j) {
        const float s2 = bn2_g[j] * rsqrtf(bn2_v[j] + EPSB);
        outc += (bn2_b[j] - bn2_m[j] * s2) * w_out[j];
    }

    float c = 0.f, h = 0.f;
    for (int t = 0; t < TT; ++t) {
        float a = s_g[t][lane];
        #pragma unroll
        for (int j = 0; j < UU; ++j)
            a += __shfl_sync(0xffffffffu, h, j) * wcol[FF + j];

        const float fg = fsig (__shfl_sync(0xffffffffu, a, u));
        const float ig = fsig (__shfl_sync(0xffffffffu, a, u + 8));
        const float gg = ftanh(__shfl_sync(0xffffffffu, a, u + 16));
        const float og = fsig (__shfl_sync(0xffffffffu, a, u + 24));
        c = fg * c + ig * gg;
        h = og * ftanh(c);

        float p = h * coef;
        p += __shfl_xor_sync(0xffffffffu, p, 1);
        p += __shfl_xor_sync(0xffffffffu, p, 2);
        p += __shfl_xor_sync(0xffffffffu, p, 4);
        if (lane == 0) out[(b << 5) + t] = p + outc;
    }
}

// ---------------------------------------------------------------------------
// Launch
// ---------------------------------------------------------------------------
extern "C" void kernel_launch(void* const* d_in, const int* in_sizes, int n_in,
                              void* d_out, int out_size)
{
    const float* x     = (const float*)d_in[0];
    const float* w1    = (const float*)d_in[1];
    const float* b1    = (const float*)d_in[2];
    const float* w2    = (const float*)d_in[3];
    const float* b2    = (const float*)d_in[4];
    const float* w3    = (const float*)d_in[5];
    const float* b3    = (const float*)d_in[6];
    const float* bn1_g = (const float*)d_in[7];
    const float* bn1_b = (const float*)d_in[8];
    const float* bn1_m = (const float*)d_in[9];
    const float* bn1_v = (const float*)d_in[10];
    const float* wf    = (const float*)d_in[11];
    const float* bf    = (const float*)d_in[12];
    const float* wi1   = (const float*)d_in[13];
    const float* bi1   = (const float*)d_in[14];
    const float* wi2   = (const float*)d_in[15];
    const float* bi2   = (const float*)d_in[16];
    const float* wo    = (const float*)d_in[17];
    const float* bo    = (const float*)d_in[18];
    const float* bn2_g = (const float*)d_in[19];
    const float* bn2_b = (const float*)d_in[20];
    const float* bn2_m = (const float*)d_in[21];
    const float* bn2_v = (const float*)d_in[22];
    const float* w_out = (const float*)d_in[23];
    const float* b_out = (const float*)d_in[24];
    float* out = (float*)d_out;

    cudaFuncSetAttribute(convmm_kernel<0>, cudaFuncAttributeMaxDynamicSharedMemorySize, CONV_SMEM);
    cudaFuncSetAttribute(convmm_kernel<1>, cudaFuncAttributeMaxDynamicSharedMemorySize, CONV_SMEM);

    __half *a1 = nullptr, *a2 = nullptr;
    uint32_t* bfrag = nullptr;
    cudaGetSymbolAddress((void**)&a1, g_a1);
    cudaGetSymbolAddress((void**)&a2, g_a2);
    cudaGetSymbolAddress((void**)&bfrag, g_bfrag);

    prep_kernel<<<2, 256>>>(w2, w3);
    conv1_kernel<<<NFRAMES, 256>>>(x, w1, b1);
    convmm_kernel<0><<<GRID_CONV, 256, CONV_SMEM>>>(a1, bfrag, b2);
    convmm_kernel<1><<<GRID_CONV, 256, CONV_SMEM>>>(a2, bfrag + 27 * 6 * 64, b3);
    lstm_kernel<<<BB, 32>>>(wf, bf, wi1, bi1, wi2, bi2, wo, bo,
                            bn1_g, bn1_b, bn1_m, bn1_v,
                            bn2_g, bn2_b, bn2_m, bn2_v,
                            w_out, b_out, out);
}

// round 11
// speedup vs baseline: 6.2795x; 1.0160x over previous
#include <cuda_runtime.h>
#include <cuda_fp16.h>
#include <cstdint>
#include <math.h>

// Problem constants
#define BB   32
#define TT   32
#define HH   28
#define WW   28
#define FF   48
#define UU   8
#define EPSB 1e-3f
#define NFRAMES (BB*TT)            // 1024
#define FRAME_PIX (HH*WW)          // 784
#define PW   30                    // padded width
#define PROWS (PW*PW)              // 900 padded pixel-rows per frame

// ---------------------------------------------------------------------------
// Warp-MMA helpers
// ---------------------------------------------------------------------------
__device__ __forceinline__ uint32_t smem_u32(const void* p) {
    return (uint32_t)__cvta_generic_to_shared(p);
}
__device__ __forceinline__ void ldmx4(uint32_t a[4], uint32_t addr) {
    asm volatile("ldmatrix.sync.aligned.m8n8.x4.shared.b16 {%0,%1,%2,%3}, [%4];"
                 : "=r"(a[0]), "=r"(a[1]), "=r"(a[2]), "=r"(a[3]) : "r"(addr));
}
__device__ __forceinline__ void mma_fp16(float c[4], const uint32_t a[4],
                                         uint32_t b0, uint32_t b1) {
    asm volatile("mma.sync.aligned.m16n8k16.row.col.f32.f16.f16.f32 "
                 "{%0,%1,%2,%3},{%4,%5,%6,%7},{%8,%9},{%0,%1,%2,%3};"
                 : "+f"(c[0]), "+f"(c[1]), "+f"(c[2]), "+f"(c[3])
                 : "r"(a[0]), "r"(a[1]), "r"(a[2]), "r"(a[3]), "r"(b0), "r"(b1));
}
__device__ __forceinline__ void cpa16(uint32_t dst, const void* src, uint32_t srcbytes) {
    asm volatile("cp.async.cg.shared.global [%0], [%1], 16, %2;"
                 :: "r"(dst), "l"(src), "r"(srcbytes));
}
#define CPA_COMMIT() asm volatile("cp.async.commit_group;" ::: "memory")
#define CPA_WAIT(n)  asm volatile("cp.async.wait_group %0;" :: "n"(n) : "memory")

// ---------------------------------------------------------------------------
// Scratch
// ---------------------------------------------------------------------------
__device__ __align__(16) __half g_a1[NFRAMES * PROWS * FF];
__device__ __align__(16) __half g_a2[NFRAMES * PROWS * FF];
__device__ __align__(16) uint32_t g_bfrag[2][27 * 6 * 64];  // fp16x2 fragments
__device__ float g_feats[NFRAMES * 4 * FF];   // per-(frame,quarter) pooled partials

// ---------------------------------------------------------------------------
// Kernel 0: pre-fragment conv weights (once per run)
// ---------------------------------------------------------------------------
__global__ void prep_kernel(const float* __restrict__ w2,
                            const float* __restrict__ w3)
{
    const float* w = (blockIdx.x == 0) ? w2 : w3;
    uint32_t* dst = g_bfrag[blockIdx.x];
    for (int i = threadIdx.x; i < 162 * 64; i += 256) {
        const int group = i >> 6;
        const int slot  = i & 63;
        const int l     = slot >> 1;
        const int reg   = slot & 1;
        const int tapkc = group / 6;
        const int nt    = group - tapkc * 6;
        const int tap   = tapkc / 3;
        const int kc    = tapkc - tap * 3;
        const int n     = nt * 8 + (l >> 2);
        const int k     = kc * 16 + (l & 3) * 2 + reg * 8;
        const __half h0 = __float2half_rn(w[(tap * FF + k)     * FF + n]);
        const __half h1 = __float2half_rn(w[(tap * FF + k + 1) * FF + n]);
        dst[i] = (uint32_t)__half_as_ushort(h0) | ((uint32_t)__half_as_ushort(h1) << 16);
    }
}

// ---------------------------------------------------------------------------
// Kernel 1: conv1 (C=1 -> 48) + ReLU. Zero-padded smem image, float2 weights,
// half2 stores.
// ---------------------------------------------------------------------------
__global__ void __launch_bounds__(256, 1)
conv1_kernel(const float* __restrict__ x,
             const float* __restrict__ w1,
             const float* __restrict__ b1)
{
    __shared__ float  s_f[PROWS];          // 30x30, zero halo
    __shared__ float2 s_w[9 * 24];
    __shared__ float2 s_b2[24];

    const int frame = blockIdx.x;
    const int tid   = threadIdx.x;

    for (int i = tid; i < PROWS; i += 256) {
        const int r = i / PW, c = i - r * PW;
        float v = 0.f;
        if (r >= 1 && r <= HH && c >= 1 && c <= WW)
            v = x[frame * FRAME_PIX + (r - 1) * WW + (c - 1)];
        s_f[i] = v;
    }
    for (int i = tid; i < 9 * 24; i += 256) s_w[i] = ((const float2*)w1)[i];
    if (tid < 24) s_b2[tid] = ((const float2*)b1)[tid];
    __syncthreads();

    uint32_t* outp = (uint32_t*)(g_a1 + (size_t)frame * PROWS * FF);
    for (int idx = tid; idx < FRAME_PIX * 24; idx += 256) {
        const int p   = idx / 24;
        const int co2 = idx - p * 24;
        const int h   = p / WW;
        const int w   = p - h * WW;
        const int base = h * PW + w;
        float2 acc = s_b2[co2];
        #pragma unroll
        for (int dy = 0; dy < 3; ++dy) {
            #pragma unroll
            for (int dx = 0; dx < 3; ++dx) {
                const float v = s_f[base + dy * PW + dx];
                const float2 fw = s_w[(dy * 3 + dx) * 24 + co2];
                acc.x += v * fw.x;
                acc.y += v * fw.y;
            }
        }
        const __half2 hv = __floats2half2_rn(fmaxf(acc.x, 0.f), fmaxf(acc.y, 0.f));
        outp[((h + 1) * PW + (w + 1)) * 24 + co2] = *(const uint32_t*)&hv;
    }
}

// ---------------------------------------------------------------------------
// Kernel 2/3: persistent double-buffered conv48 via mma.sync (fp16, 1 pass).
// R11: item = QUARTER-frame (225 owned rows) -> slab 304 rows, smem/CTA
// ~107 KB -> 2 CTAs/SM (16 warps). T_PER_W=2, launch_bounds(256,2) caps
// regs at 128 so occupancy materializes. 15 tiles of 16 rows per item
// (tile slot 15 clamps to 14; dup skipped in pool path).
// ---------------------------------------------------------------------------
#define Q_ROWS    225
#define SLAB_ROWS 304                          // 31 + 14*16+15 + 31 = 301 -> pad 304
#define A_STRIDE  112
#define A_BYTES   (SLAB_ROWS * A_STRIDE)       // 34048
#define B_BYTES   (27 * 6 * 64 * 4)            // 41472
#define OFF_A0    0
#define OFF_A1    (OFF_A0 + A_BYTES)           // 34048
#define OFF_B     (OFF_A1 + A_BYTES)           // 68096
#define OFF_BI    (OFF_B + B_BYTES)            // 109568
#define CONV_SMEM (OFF_BI + FF * 4)            // 109760
#define MT_MAX    14                           // last valid tile index
#define T_PER_W   2
#define GRID_CONV 296                          // 2 CTAs/SM x 148
#define N_ITEMS   (NFRAMES * 4)                // 4096 quarter-frames

__device__ __forceinline__ void issue_slab(uint32_t dst, const __half* __restrict__ in,
                                           int item, int tid)
{
    const int frame = item >> 2;
    const int rbase = (item & 3) * Q_ROWS;
    const char* src = (const char*)(in + (size_t)frame * PROWS * FF);
    for (int i = tid; i < SLAB_ROWS * 7; i += 256) {
        const int s   = i / 7;
        const int blk = i - s * 7;
        const int r   = rbase - 31 + s;
        bool valid = false;
        if (r >= 0 && r < PROWS && blk < 6) {
            const int rd = r / PW, rm = r - rd * PW;
            valid = (rd >= 1 && rd <= HH && rm >= 1 && rm <= WW);
        }
        const long off = valid ? ((long)r * 96 + blk * 16) : 0;
        cpa16(dst + s * A_STRIDE + blk * 16, src + off, valid ? 16u : 0u);
    }
}

template <int PHASE>
__global__ void __launch_bounds__(256, 2)
convmm_kernel(const __half* __restrict__ in,
              const uint32_t* __restrict__ bfrag,
              const float* __restrict__ bias)
{
    extern __shared__ __align__(16) char smem[];
    __shared__ float s_pool[8 * FF];

    const int bid  = blockIdx.x;
    const int tid  = threadIdx.x;
    const int wid  = tid >> 5;
    const int lane = tid & 31;
    const uint32_t smb = smem_u32(smem);
    const int nItems = (N_ITEMS - bid + GRID_CONV - 1) / GRID_CONV;

    float* s_bias = (float*)(smem + OFF_BI);
    if (tid < FF) s_bias[tid] = bias[tid];

    // Group 0: B fragments + first A slab
    for (int i = tid; i < B_BYTES / 16; i += 256)
        cpa16(smb + OFF_B + i * 16, (const char*)bfrag + i * 16, 16);
    if (nItems > 0) issue_slab(smb + OFF_A0, in, bid, tid);
    CPA_COMMIT();

    const uint32_t laneoff = (uint32_t)((lane & 15) * A_STRIDE + ((lane >> 4) << 4));
    const uint32_t* s_b = (const uint32_t*)(smem + OFF_B);

    for (int k = 0; k < nItems; ++k) {
        const int item  = bid + GRID_CONV * k;
        const int frame = item >> 2;
        const int rbase = (item & 3) * Q_ROWS;
        const uint32_t abuf = smb + ((k & 1) ? OFF_A1 : OFF_A0);

        if (k + 1 < nItems) {
            issue_slab(smb + ((k & 1) ? OFF_A0 : OFF_A1), in, item + GRID_CONV, tid);
            CPA_COMMIT();
            CPA_WAIT(1);
        } else {
            CPA_WAIT(0);
        }
        __syncthreads();

        // Per-warp tiles (slots wid, wid+8; clamp; dup skipped in pool path)
        int mtv[T_PER_W];
        uint32_t abase[T_PER_W];
        #pragma unroll
        for (int i = 0; i < T_PER_W; ++i) {
            int mt = wid + 8 * i;
            mtv[i] = mt;
            if (mt > MT_MAX) mt = MT_MAX;
            abase[i] = abuf + (uint32_t)((31 + mt * 16) * A_STRIDE) + laneoff;
        }

        float C[T_PER_W][6][4];
        #pragma unroll
        for (int i = 0; i < T_PER_W; ++i)
            #pragma unroll
            for (int nt = 0; nt < 6; ++nt) {
                C[i][nt][0] = 0.f; C[i][nt][1] = 0.f; C[i][nt][2] = 0.f; C[i][nt][3] = 0.f;
            }

        #pragma unroll 1
        for (int tap = 0; tap < 9; ++tap) {
            const int dy = tap / 3;
            const int aoff = ((dy - 1) * PW + (tap - dy * 3) - 1) * A_STRIDE;
            #pragma unroll
            for (int kc = 0; kc < 3; ++kc) {
                uint2 BW[6];
                const int bbase = ((tap * 3 + kc) * 6) * 64 + lane * 2;
                #pragma unroll
                for (int nt = 0; nt < 6; ++nt)
                    BW[nt] = *(const uint2*)(s_b + bbase + nt * 64);
                #pragma unroll
                for (int i = 0; i < T_PER_W; ++i) {
                    uint32_t a[4];
                    ldmx4(a, abase[i] + (uint32_t)(aoff + kc * 32));
                    #pragma unroll
                    for (int nt = 0; nt < 6; ++nt)
                        mma_fp16(C[i][nt], a, BW[nt].x, BW[nt].y);
                }
            }
        }

        // ---- Epilogue ----
        float pool[6][2];
        if (PHASE == 1) {
            #pragma unroll
            for (int nt = 0; nt < 6; ++nt) { pool[nt][0] = 0.f; pool[nt][1] = 0.f; }
        }

        #pragma unroll
        for (int i = 0; i < T_PER_W; ++i) {
            if (mtv[i] > MT_MAX) continue;
            #pragma unroll
            for (int rh = 0; rh < 2; ++rh) {
                const int r = rbase + mtv[i] * 16 + (lane >> 2) + rh * 8;
                if (PHASE == 0) {
                    if (r < PROWS) {
                        uint32_t* d = (uint32_t*)(g_a2 + ((size_t)frame * PROWS + r) * FF);
                        #pragma unroll
                        for (int nt = 0; nt < 6; ++nt) {
                            const int co = nt * 8 + (lane & 3) * 2;
                            const __half h0 = __float2half_rn(fmaxf(C[i][nt][rh * 2]     + s_bias[co],     0.f));
                            const __half h1 = __float2half_rn(fmaxf(C[i][nt][rh * 2 + 1] + s_bias[co + 1], 0.f));
                            d[co >> 1] = (uint32_t)__half_as_ushort(h0) | ((uint32_t)__half_as_ushort(h1) << 16);
                        }
                    }
                } else {
                    bool valid = false;
                    if ((r - rbase) < Q_ROWS && r < PROWS) {
                        const int rd = r / PW, rm = r - rd * PW;
                        valid = (rd >= 1 && rd <= HH && rm >= 1 && rm <= WW);
                    }
                    if (valid) {
                        #pragma unroll
                        for (int nt = 0; nt < 6; ++nt) {
                            const int co = nt * 8 + (lane & 3) * 2;
                            pool[nt][0] += fmaxf(C[i][nt][rh * 2]     + s_bias[co],     0.f);
                            pool[nt][1] += fmaxf(C[i][nt][rh * 2 + 1] + s_bias[co + 1], 0.f);
                        }
                    }
                }
            }
        }

        if (PHASE == 1) {
            #pragma unroll
            for (int nt = 0; nt < 6; ++nt) {
                #pragma unroll
                for (int e = 0; e < 2; ++e) {
                    float v = pool[nt][e];
                    v += __shfl_xor_sync(0xffffffffu, v, 4);
                    v += __shfl_xor_sync(0xffffffffu, v, 8);
                    v += __shfl_xor_sync(0xffffffffu, v, 16);
                    if ((lane >> 2) == 0)
                        s_pool[wid * FF + nt * 8 + lane * 2 + e] = v;
                }
            }
            __syncthreads();
            if (tid < FF) {
                float s = 0.f;
                #pragma unroll
                for (int ww = 0; ww < 8; ++ww) s += s_pool[ww * FF + tid];
                g_feats[(frame * 4 + (item & 3)) * FF + tid] = s;
            }
        }
        __syncthreads();   // all reads of abuf done before it is refilled
    }
}

// ---------------------------------------------------------------------------
// Kernel 4: LSTM + BN2 + head. One warp per batch element.
// ---------------------------------------------------------------------------
__device__ __forceinline__ float fsig(float x)  { return __fdividef(1.f, 1.f + __expf(-x)); }
__device__ __forceinline__ float ftanh(float x) { return 1.f - __fdividef(2.f, __expf(2.f * x) + 1.f); }

__global__ void __launch_bounds__(32, 1)
lstm_kernel(const float* __restrict__ wf,  const float* __restrict__ bf,
            const float* __restrict__ wi1, const float* __restrict__ bi1,
            const float* __restrict__ wi2, const float* __restrict__ bi2,
            const float* __restrict__ wo,  const float* __restrict__ bo,
            const float* __restrict__ bn1_g, const float* __restrict__ bn1_b,
            const float* __restrict__ bn1_m, const float* __restrict__ bn1_v,
            const float* __restrict__ bn2_g, const float* __restrict__ bn2_b,
            const float* __restrict__ bn2_m, const float* __restrict__ bn2_v,
            const float* __restrict__ w_out, const float* __restrict__ b_out,
            float* __restrict__ out)
{
    __shared__ float s_x[TT][FF];
    __shared__ float s_g[TT][32];
    __shared__ float s_sc1[FF], s_sh1[FF];

    const int b    = blockIdx.x;
    const int lane = threadIdx.x;
    const int u    = lane & 7;

    const float* Wg = (lane < 8) ? wf : (lane < 16) ? wi1 : (lane < 24) ? wi2 : wo;
    const float* Bg = (lane < 8) ? bf : (lane < 16) ? bi1 : (lane < 24) ? bi2 : bo;
    float wcol[FF + UU];
    #pragma unroll
    for (int k = 0; k < FF + UU; ++k) wcol[k] = Wg[k * UU + u];
    const float bgate = Bg[u];

    for (int co = lane; co < FF; co += 32) {
        const float sc = bn1_g[co] * rsqrtf(bn1_v[co] + EPSB);
        s_sc1[co] = sc * (1.f / (float)FRAME_PIX);
        s_sh1[co] = bn1_b[co] - bn1_m[co] * sc;
    }
    __syncwarp();

    for (int i = lane; i < TT * FF; i += 32) {
        const int t = i / FF, co = i - t * FF;
        const int fr = (b << 5) + t;
        const float ps = g_feats[(fr * 4 + 0) * FF + co] + g_feats[(fr * 4 + 1) * FF + co]
                       + g_feats[(fr * 4 + 2) * FF + co] + g_feats[(fr * 4 + 3) * FF + co];
        s_x[t][co] = ps * s_sc1[co] + s_sh1[co];
    }
    __syncwarp();

    #pragma unroll 4
    for (int t = 0; t < TT; ++t) {
        float a0 = 0.f, a1 = 0.f, a2 = 0.f, a3 = 0.f;
        #pragma unroll
        for (int k = 0; k < FF; k += 4) {
            a0 += s_x[t][k]     * wcol[k];
            a1 += s_x[t][k + 1] * wcol[k + 1];
            a2 += s_x[t][k + 2] * wcol[k + 2];
            a3 += s_x[t][k + 3] * wcol[k + 3];
        }
        s_g[t][lane] = bgate + ((a0 + a1) + (a2 + a3));
    }
    __syncwarp();

    const float sc2  = bn2_g[u] * rsqrtf(bn2_v[u] + EPSB);
    const float coef = sc2 * w_out[u];
    float outc = b_out[0];
    #pragma unroll
    for (int j = 0; j < UU; ++j) {
        const float s2 = bn2_g[j] * rsqrtf(bn2_v[j] + EPSB);
        outc += (bn2_b[j] - bn2_m[j] * s2) * w_out[j];
    }

    float c = 0.f, h = 0.f;
    for (int t = 0; t < TT; ++t) {
        float a = s_g[t][lane];
        #pragma unroll
        for (int j = 0; j < UU; ++j)
            a += __shfl_sync(0xffffffffu, h, j) * wcol[FF + j];

        const float fg = fsig (__shfl_sync(0xffffffffu, a, u));
        const float ig = fsig (__shfl_sync(0xffffffffu, a, u + 8));
        const float gg = ftanh(__shfl_sync(0xffffffffu, a, u + 16));
        const float og = fsig (__shfl_sync(0xffffffffu, a, u + 24));
        c = fg * c + ig * gg;
        h = og * ftanh(c);

        float p = h * coef;
        p += __shfl_xor_sync(0xffffffffu, p, 1);
        p += __shfl_xor_sync(0xffffffffu, p, 2);
        p += __shfl_xor_sync(0xffffffffu, p, 4);
        if (lane == 0) out[(b << 5) + t] = p + outc;
    }
}

// ---------------------------------------------------------------------------
// Launch
// ---------------------------------------------------------------------------
extern "C" void kernel_launch(void* const* d_in, const int* in_sizes, int n_in,
                              void* d_out, int out_size)
{
    const float* x     = (const float*)d_in[0];
    const float* w1    = (const float*)d_in[1];
    const float* b1    = (const float*)d_in[2];
    const float* w2    = (const float*)d_in[3];
    const float* b2    = (const float*)d_in[4];
    const float* w3    = (const float*)d_in[5];
    const float* b3    = (const float*)d_in[6];
    const float* bn1_g = (const float*)d_in[7];
    const float* bn1_b = (const float*)d_in[8];
    const float* bn1_m = (const float*)d_in[9];
    const float* bn1_v = (const float*)d_in[10];
    const float* wf    = (const float*)d_in[11];
    const float* bf    = (const float*)d_in[12];
    const float* wi1   = (const float*)d_in[13];
    const float* bi1   = (const float*)d_in[14];
    const float* wi2   = (const float*)d_in[15];
    const float* bi2   = (const float*)d_in[16];
    const float* wo    = (const float*)d_in[17];
    const float* bo    = (const float*)d_in[18];
    const float* bn2_g = (const float*)d_in[19];
    const float* bn2_b = (const float*)d_in[20];
    const float* bn2_m = (const float*)d_in[21];
    const float* bn2_v = (const float*)d_in[22];
    const float* w_out = (const float*)d_in[23];
    const float* b_out = (const float*)d_in[24];
    float* out = (float*)d_out;

    cudaFuncSetAttribute(convmm_kernel<0>, cudaFuncAttributeMaxDynamicSharedMemorySize, CONV_SMEM);
    cudaFuncSetAttribute(convmm_kernel<1>, cudaFuncAttributeMaxDynamicSharedMemorySize, CONV_SMEM);

    __half *a1 = nullptr, *a2 = nullptr;
    uint32_t* bfrag = nullptr;
    cudaGetSymbolAddress((void**)&a1, g_a1);
    cudaGetSymbolAddress((void**)&a2, g_a2);
    cudaGetSymbolAddress((void**)&bfrag, g_bfrag);

    prep_kernel<<<2, 256>>>(w2, w3);
    conv1_kernel<<<NFRAMES, 256>>>(x, w1, b1);
    convmm_kernel<0><<<GRID_CONV, 256, CONV_SMEM>>>(a1, bfrag, b2);
    convmm_kernel<1><<<GRID_CONV, 256, CONV_SMEM>>>(a2, bfrag + 27 * 6 * 64, b3);
    lstm_kernel<<<BB, 32>>>(wf, bf, wi1, bi1, wi2, bi2, wo, bo,
                            bn1_g, bn1_b, bn1_m, bn1_v,
                            bn2_g, bn2_b, bn2_m, bn2_v,
                            w_out, b_out, out);
}